// round 7
// baseline (speedup 1.0000x reference)
#include <cuda_runtime.h>
#include <cuda_bf16.h>
#include <math.h>
#include <stdint.h>

#define HID 256
#define NNODES 8192
#define BSESS 512
#define NITEMS 100000
#define NITEMS_PAD 100096           // 391 * 256

// ---------------- static scratch (floats) ----------------
constexpr size_t NH = (size_t)NNODES * HID;
constexpr size_t F_H    = 0;
constexpr size_t F_Z    = F_H   + NH;
constexpr size_t F_Q2   = F_Z   + NH;
constexpr size_t F_P    = F_Q2  + NH;                 // 2 x NH partials
constexpr size_t F_Q1S  = F_P   + 2 * NH;
constexpr size_t F_SG   = F_Q1S + (size_t)BSESS * HID;
constexpr size_t F_W1T  = F_SG  + (size_t)BSESS * HID;
constexpr size_t F_W2T  = F_W1T + (size_t)HID * HID;
constexpr size_t F_WF1T = F_W2T + (size_t)HID * HID;
constexpr size_t F_WF2T = F_WF1T + (size_t)HID * HID;
constexpr size_t F_WF4T = F_WF2T + (size_t)HID * HID;
constexpr size_t F_MAX  = F_WF4T + (size_t)2 * HID * HID;
constexpr size_t F_SUM  = F_MAX + BSESS;
constexpr size_t F_TOTAL = F_SUM + BSESS;
__device__ float g_f[F_TOTAL];

// bf16 hi/lo split buffers
__device__ __nv_bfloat16 g_adj_h[(size_t)NNODES * NNODES];
__device__ __nv_bfloat16 g_adj_l[(size_t)NNODES * NNODES];
__device__ __nv_bfloat16 g_emb_h[(size_t)NITEMS_PAD * HID];
__device__ __nv_bfloat16 g_emb_l[(size_t)NITEMS_PAD * HID];
__device__ __nv_bfloat16 g_x_h[(size_t)HID * NNODES];
__device__ __nv_bfloat16 g_x_l[(size_t)HID * NNODES];
__device__ __nv_bfloat16 g_sh_h[(size_t)BSESS * HID];
__device__ __nv_bfloat16 g_sh_l[(size_t)BSESS * HID];

// ---------------- PTX helpers ----------------
__device__ __forceinline__ uint32_t smem_u32(const void* p) {
    uint32_t a;
    asm("{ .reg .u64 t; cvta.to.shared.u64 t, %1; cvt.u32.u64 %0, t; }" : "=r"(a) : "l"(p));
    return a;
}
#define LDM_X4(r, a) \
    asm volatile("ldmatrix.sync.aligned.m8n8.x4.shared.b16 {%0,%1,%2,%3}, [%4];" \
        : "=r"((r)[0]), "=r"((r)[1]), "=r"((r)[2]), "=r"((r)[3]) : "r"(a))
#define MMA16816(c, a, b0, b1) \
    asm volatile("mma.sync.aligned.m16n8k16.row.col.f32.bf16.bf16.f32 " \
        "{%0,%1,%2,%3}, {%4,%5,%6,%7}, {%8,%9}, {%0,%1,%2,%3};" \
        : "+f"((c)[0]), "+f"((c)[1]), "+f"((c)[2]), "+f"((c)[3]) \
        : "r"((a)[0]), "r"((a)[1]), "r"((a)[2]), "r"((a)[3]), "r"(b0), "r"(b1))
#define CP_ASYNC16(dst, src) \
    asm volatile("cp.async.cg.shared.global [%0], [%1], 16;" :: "r"(dst), "l"(src) : "memory")
#define CP_COMMIT() asm volatile("cp.async.commit_group;" ::: "memory")
#define CP_WAIT1()  asm volatile("cp.async.wait_group 1;" ::: "memory")
#define CP_WAIT0()  asm volatile("cp.async.wait_group 0;" ::: "memory")

// ---------------- fp32 -> bf16 hi/lo split ----------------
__global__ void cvt_split(const float* __restrict__ src, __nv_bfloat16* __restrict__ hi,
                          __nv_bfloat16* __restrict__ lo, size_t nsrc, size_t ntot)
{
    size_t stride = (size_t)gridDim.x * blockDim.x;
    for (size_t t = (size_t)blockIdx.x * blockDim.x + threadIdx.x; t * 4 < ntot; t += stride) {
        size_t i = t * 4;
        float4 v = (i < nsrc) ? *(const float4*)(src + i) : make_float4(0.f, 0.f, 0.f, 0.f);
        float f[4] = {v.x, v.y, v.z, v.w};
        __nv_bfloat16 h[4], l[4];
        #pragma unroll
        for (int j = 0; j < 4; j++) {
            h[j] = __float2bfloat16_rn(f[j]);
            l[j] = __float2bfloat16_rn(f[j] - __bfloat162float(h[j]));
        }
        *(__nv_bfloat162*)(hi + i)     = __nv_bfloat162(h[0], h[1]);
        *(__nv_bfloat162*)(hi + i + 2) = __nv_bfloat162(h[2], h[3]);
        *(__nv_bfloat162*)(lo + i)     = __nv_bfloat162(l[0], l[1]);
        *(__nv_bfloat162*)(lo + i + 2) = __nv_bfloat162(l[2], l[3]);
    }
}

// ---------------- bf16-split GEMM, BM=128 x BN=256, BK=32, 3 stages ----------------
// C[m][n] (+ z*partStride) = A @ B^T,  A=Ah+Al [M][K] rowmajor, B=Bh+Bl [N][K] rowmajor
// 256 threads = 8 warps (2 x 4), warp tile 64x64. blockIdx.z = K-split part.
#define SP_PITCH 80
#define SP_AMAT  10240                 // 128 * 80
#define SP_BMAT  20480                 // 256 * 80
#define SP_STAGE 61440                 // 2*AMAT + 2*BMAT
#define SP_SMEM  184320                // 3 stages

__global__ __launch_bounds__(256)
void gemm_sp2(const __nv_bfloat16* __restrict__ Ah, const __nv_bfloat16* __restrict__ Al, int lda,
              const __nv_bfloat16* __restrict__ Bh, const __nv_bfloat16* __restrict__ Bl, int ldb,
              float* __restrict__ C, size_t ldc, size_t partStride,
              int Nbound, int K)
{
    extern __shared__ __align__(128) char smem[];
    uint32_t sbase = smem_u32(smem);
    int tid = threadIdx.x, wid = tid >> 5, lane = tid & 31;
    int n0 = blockIdx.x * 256;
    int m0 = blockIdx.y * 128;
    int kbase = blockIdx.z * K;
    int wm = (wid >> 2) * 64;
    int wn = (wid & 3) * 64;

    float acc[4][8][4];
    #pragma unroll
    for (int a = 0; a < 4; a++)
        #pragma unroll
        for (int b = 0; b < 8; b++)
            #pragma unroll
            for (int cc = 0; cc < 4; cc++) acc[a][b][cc] = 0.f;

    auto copy_stage = [&](int s, int k0e) {
        uint32_t dst0 = sbase + (uint32_t)s * SP_STAGE;
        int colb = kbase + k0e;
        #pragma unroll
        for (int j = 0; j < 12; j++) {
            int c = j * 256 + tid;
            const __nv_bfloat16* g;
            uint32_t dst;
            if (c < 1024) {            // A mats: 2 x 128 rows x 4 chunks
                int mat = c >> 9, row = (c >> 2) & 127, cc = c & 3;
                g = (mat ? Al : Ah) + (size_t)(m0 + row) * lda + colb + cc * 8;
                dst = dst0 + (uint32_t)mat * SP_AMAT + (uint32_t)row * SP_PITCH + (uint32_t)cc * 16;
            } else {                   // B mats: 2 x 256 rows x 4 chunks
                int cb = c - 1024;
                int mat = cb >> 10, row = (cb >> 2) & 255, cc = cb & 3;
                g = (mat ? Bl : Bh) + (size_t)(n0 + row) * ldb + colb + cc * 8;
                dst = dst0 + 2 * SP_AMAT + (uint32_t)mat * SP_BMAT + (uint32_t)row * SP_PITCH + (uint32_t)cc * 16;
            }
            CP_ASYNC16(dst, g);
        }
    };

    int kt = K / 32;
    copy_stage(0, 0);  CP_COMMIT();
    copy_stage(1, 32); CP_COMMIT();

    for (int ki = 0; ki < kt; ki++) {
        int s = ki % 3;
        CP_WAIT1();
        __syncthreads();
        int kn = ki + 2;
        if (kn < kt) copy_stage(kn % 3, kn * 32);
        CP_COMMIT();

        uint32_t As  = sbase + (uint32_t)s * SP_STAGE;
        uint32_t Asl = As + SP_AMAT;
        uint32_t Bs  = As + 2 * SP_AMAT;
        uint32_t Bsl = Bs + SP_BMAT;

        #pragma unroll
        for (int kb = 0; kb < 32; kb += 16) {
            uint32_t ah[4][4], al[4][4], bh[4][4], bl[4][4];
            uint32_t aoff = (uint32_t)(wm + (lane & 15)) * SP_PITCH
                          + (uint32_t)(kb + ((lane >> 4) << 3)) * 2;
            #pragma unroll
            for (int mt = 0; mt < 4; mt++) {
                LDM_X4(ah[mt], As  + aoff + mt * 16 * SP_PITCH);
                LDM_X4(al[mt], Asl + aoff + mt * 16 * SP_PITCH);
            }
            uint32_t boff = (uint32_t)(wn + (lane & 7) + ((lane >> 1) & 8)) * SP_PITCH
                          + (uint32_t)(kb + ((lane >> 3) & 1) * 8) * 2;
            #pragma unroll
            for (int p = 0; p < 4; p++) {
                LDM_X4(bh[p], Bs  + boff + p * 16 * SP_PITCH);
                LDM_X4(bl[p], Bsl + boff + p * 16 * SP_PITCH);
            }
            #pragma unroll
            for (int mt = 0; mt < 4; mt++)
                #pragma unroll
                for (int nt = 0; nt < 8; nt++) {
                    int p = nt >> 1, q = (nt & 1) * 2;
                    MMA16816(acc[mt][nt], ah[mt], bh[p][q], bh[p][q + 1]);
                    MMA16816(acc[mt][nt], ah[mt], bl[p][q], bl[p][q + 1]);
                    MMA16816(acc[mt][nt], al[mt], bh[p][q], bh[p][q + 1]);
                }
        }
    }
    CP_WAIT0();

    float* Cp = C + (size_t)blockIdx.z * partStride;
    #pragma unroll
    for (int mt = 0; mt < 4; mt++)
        #pragma unroll
        for (int nt = 0; nt < 8; nt++) {
            int m = m0 + wm + mt * 16 + (lane >> 2);
            int n = n0 + wn + nt * 8 + (lane & 3) * 2;
            if (n < Nbound) {
                *(float2*)&Cp[(size_t)m * ldc + n] = make_float2(acc[mt][nt][0], acc[mt][nt][1]);
                *(float2*)&Cp[(size_t)(m + 8) * ldc + n] = make_float2(acc[mt][nt][2], acc[mt][nt][3]);
            }
        }
}

// combine split-K partials: o = op(p[i] + p[i+NH])
__global__ void combine2(const float* __restrict__ p, float* __restrict__ o, int doRelu)
{
    size_t i = (size_t)blockIdx.x * blockDim.x + threadIdx.x;
    const float4* a = (const float4*)p;
    size_t s = NH / 4;
    float4 v0 = a[i], v1 = a[i + s];
    float4 v = make_float4(v0.x + v1.x, v0.y + v1.y, v0.z + v1.z, v0.w + v1.w);
    if (doRelu) {
        v.x = fmaxf(v.x, 0.f); v.y = fmaxf(v.y, 0.f);
        v.z = fmaxf(v.z, 0.f); v.w = fmaxf(v.w, 0.f);
    }
    ((float4*)o)[i] = v;
}

// ---------------- fused transpose of the 5 weight matrices ----------------
__global__ void transpose_all(const float* __restrict__ W1, const float* __restrict__ W2,
                              const float* __restrict__ Wf1, const float* __restrict__ Wf2,
                              const float* __restrict__ Wf4,
                              float* __restrict__ o1, float* __restrict__ o2,
                              float* __restrict__ o3, float* __restrict__ o4,
                              float* __restrict__ o5)
{
    int zid = blockIdx.z;
    const float* W = (zid == 0) ? W1 : (zid == 1) ? W2 : (zid == 2) ? Wf1 : (zid == 3) ? Wf2 : Wf4;
    float* Wt      = (zid == 0) ? o1 : (zid == 1) ? o2 : (zid == 2) ? o3 : (zid == 3) ? o4 : o5;
    int R = HID, C = (zid == 4) ? 2 * HID : HID;
    __shared__ float tile[32][33];
    int c0 = blockIdx.x * 32, r0 = blockIdx.y * 32;
    if (c0 >= C) return;
    int x = threadIdx.x, y = threadIdx.y;
    #pragma unroll
    for (int dy = 0; dy < 32; dy += 8) {
        int r = r0 + y + dy, c = c0 + x;
        if (r < R && c < C) tile[y + dy][x] = W[(size_t)r * C + c];
    }
    __syncthreads();
    #pragma unroll
    for (int dy = 0; dy < 32; dy += 8) {
        int c = c0 + y + dy, r = r0 + x;
        if (c < C && r < R) Wt[(size_t)c * R + r] = tile[x][y + dy];
    }
}

// ---------------- fp32 tiled GEMM (small GEMMs; optional split-bf16 transC output) ----------------
#define BM 128
#define BN 128
#define BK 16
__global__ __launch_bounds__(256)
void gemm_tiled(const float* __restrict__ A, int lda, const int* __restrict__ gidx,
                const float* __restrict__ B, int ldb, const float* __restrict__ bias,
                float* __restrict__ C, __nv_bfloat16* __restrict__ hiC, __nv_bfloat16* __restrict__ loC,
                int ldc, int M, int N, int K, int doRelu, int transC)
{
    __shared__ __align__(16) float As[BK][BM];
    __shared__ __align__(16) float Bs[BK][BN];
    int tid = threadIdx.x;
    int tx = tid & 15, ty = tid >> 4;
    int m0 = blockIdx.y * BM, n0 = blockIdx.x * BN;
    int ai = transC ? tx : ty, bi = transC ? ty : tx;
    int ai4 = ai * 4, bi4 = bi * 4;
    float acc[8][8];
    #pragma unroll
    for (int i = 0; i < 8; i++)
        #pragma unroll
        for (int j = 0; j < 8; j++) acc[i][j] = 0.f;
    int arow = tid >> 2, acol = (tid & 3) * 4;
    int r0i = m0 + arow, r1i = m0 + arow + 64;
    bool v0 = r0i < M, v1 = r1i < M;
    int gr0 = r0i, gr1 = r1i;
    if (gidx) { if (v0) gr0 = gidx[r0i]; if (v1) gr1 = gidx[r1i]; }
    const float* Arow0 = A + (size_t)gr0 * lda;
    const float* Arow1 = A + (size_t)gr1 * lda;
    int brow = tid >> 5, bcol = (tid & 31) * 4;
    for (int k0 = 0; k0 < K; k0 += BK) {
        float4 a0 = v0 ? *(const float4*)(Arow0 + k0 + acol) : make_float4(0, 0, 0, 0);
        float4 a1 = v1 ? *(const float4*)(Arow1 + k0 + acol) : make_float4(0, 0, 0, 0);
        float4 b0 = *(const float4*)(B + (size_t)(k0 + brow) * ldb + n0 + bcol);
        float4 b1 = *(const float4*)(B + (size_t)(k0 + brow + 8) * ldb + n0 + bcol);
        As[acol + 0][arow] = a0.x; As[acol + 1][arow] = a0.y;
        As[acol + 2][arow] = a0.z; As[acol + 3][arow] = a0.w;
        As[acol + 0][arow + 64] = a1.x; As[acol + 1][arow + 64] = a1.y;
        As[acol + 2][arow + 64] = a1.z; As[acol + 3][arow + 64] = a1.w;
        *(float4*)&Bs[brow][bcol] = b0;
        *(float4*)&Bs[brow + 8][bcol] = b1;
        __syncthreads();
        #pragma unroll
        for (int k = 0; k < BK; k++) {
            float4 aa0 = *(const float4*)&As[k][ai4];
            float4 aa1 = *(const float4*)&As[k][64 + ai4];
            float4 bb0 = *(const float4*)&Bs[k][bi4];
            float4 bb1 = *(const float4*)&Bs[k][64 + bi4];
            float af[8] = {aa0.x, aa0.y, aa0.z, aa0.w, aa1.x, aa1.y, aa1.z, aa1.w};
            float bf[8] = {bb0.x, bb0.y, bb0.z, bb0.w, bb1.x, bb1.y, bb1.z, bb1.w};
            #pragma unroll
            for (int i = 0; i < 8; i++)
                #pragma unroll
                for (int j = 0; j < 8; j++) acc[i][j] += af[i] * bf[j];
        }
        __syncthreads();
    }
    if (!transC) {
        #pragma unroll
        for (int i8 = 0; i8 < 8; i8++) {
            int m = m0 + ((i8 < 4) ? (ai4 + i8) : (64 + ai4 + i8 - 4));
            if (m >= M) continue;
            #pragma unroll
            for (int jg = 0; jg < 2; jg++) {
                int n = n0 + jg * 64 + bi4;
                float4 v = make_float4(acc[i8][jg*4], acc[i8][jg*4+1], acc[i8][jg*4+2], acc[i8][jg*4+3]);
                if (bias) { v.x += bias[n]; v.y += bias[n+1]; v.z += bias[n+2]; v.w += bias[n+3]; }
                if (doRelu) { v.x = fmaxf(v.x, 0.f); v.y = fmaxf(v.y, 0.f); v.z = fmaxf(v.z, 0.f); v.w = fmaxf(v.w, 0.f); }
                *(float4*)&C[(size_t)m * ldc + n] = v;
            }
        }
    } else {
        #pragma unroll
        for (int j8 = 0; j8 < 8; j8++) {
            int n = n0 + ((j8 < 4) ? (bi4 + j8) : (64 + bi4 + j8 - 4));
            float bv = bias ? bias[n] : 0.f;
            #pragma unroll
            for (int ig = 0; ig < 2; ig++) {
                int m = m0 + ig * 64 + ai4;
                if (m >= M) continue;
                float v[4] = {acc[ig*4][j8]+bv, acc[ig*4+1][j8]+bv, acc[ig*4+2][j8]+bv, acc[ig*4+3][j8]+bv};
                if (hiC) {
                    __nv_bfloat16 hh[4], ll[4];
                    #pragma unroll
                    for (int q = 0; q < 4; q++) {
                        hh[q] = __float2bfloat16_rn(v[q]);
                        ll[q] = __float2bfloat16_rn(v[q] - __bfloat162float(hh[q]));
                    }
                    size_t off = (size_t)n * ldc + m;
                    *(__nv_bfloat162*)(hiC + off)     = __nv_bfloat162(hh[0], hh[1]);
                    *(__nv_bfloat162*)(hiC + off + 2) = __nv_bfloat162(hh[2], hh[3]);
                    *(__nv_bfloat162*)(loC + off)     = __nv_bfloat162(ll[0], ll[1]);
                    *(__nv_bfloat162*)(loC + off + 2) = __nv_bfloat162(ll[2], ll[3]);
                } else {
                    *(float4*)&C[(size_t)n * ldc + m] = make_float4(v[0], v[1], v[2], v[3]);
                }
            }
        }
    }
}

__global__ void zero_k(float* p, int n)
{
    for (int i = blockIdx.x * blockDim.x + threadIdx.x; i < n; i += gridDim.x * blockDim.x)
        p[i] = 0.f;
}

// ---------------- attention / pooling / softmax ----------------
__global__ void alpha_scatter(const float* __restrict__ q1s, const float* __restrict__ q2,
                              const float* __restrict__ z, const float* __restrict__ Wf3,
                              const int* __restrict__ idx, float* __restrict__ sg)
{
    int n = blockIdx.x, c = threadIdx.x;
    int b = idx[n];
    float q = q1s[b * HID + c] + q2[(size_t)n * HID + c];
    float t = Wf3[c] / (1.f + __expf(-q));
    #pragma unroll
    for (int o = 16; o > 0; o >>= 1) t += __shfl_xor_sync(0xffffffffu, t, o);
    __shared__ float red[8];
    if ((c & 31) == 0) red[c >> 5] = t;
    __syncthreads();
    float alpha = red[0] + red[1] + red[2] + red[3] + red[4] + red[5] + red[6] + red[7];
    atomicAdd(&sg[b * HID + c], alpha * z[(size_t)n * HID + c]);
}

__global__ void sh_kernel(const float* __restrict__ z, const int* __restrict__ last_item,
                          const float* __restrict__ sg, const float* __restrict__ wf4t,
                          const float* __restrict__ bf4,
                          __nv_bfloat16* __restrict__ shh, __nv_bfloat16* __restrict__ shl)
{
    int b = blockIdx.x, c = threadIdx.x;
    __shared__ float srow[2 * HID];
    int li = last_item[b];
    srow[c]       = z[(size_t)li * HID + c];
    srow[HID + c] = sg[b * HID + c];
    __syncthreads();
    float acc = bf4[c];
    #pragma unroll 8
    for (int k = 0; k < 2 * HID; k++) acc += srow[k] * wf4t[k * HID + c];
    __nv_bfloat16 hh = __float2bfloat16_rn(acc);
    shh[b * HID + c] = hh;
    shl[b * HID + c] = __float2bfloat16_rn(acc - __bfloat162float(hh));
}

__global__ void softmax_reduce(const float* __restrict__ out,
                               float* __restrict__ gmax, float* __restrict__ gsum)
{
    int b = blockIdx.x, t = threadIdx.x;
    const float* row = out + (size_t)b * NITEMS;
    float m = -1e30f, s = 0.f;
    for (int i = t; i < NITEMS; i += 256) {
        float v = row[i];
        if (v > m) { s = s * __expf(m - v) + 1.f; m = v; }
        else       { s += __expf(v - m); }
    }
    __shared__ float sm[256], ss[256];
    sm[t] = m; ss[t] = s;
    __syncthreads();
    for (int o = 128; o > 0; o >>= 1) {
        if (t < o) {
            float m2 = sm[t + o], s2 = ss[t + o];
            float M2 = fmaxf(sm[t], m2);
            ss[t] = ss[t] * __expf(sm[t] - M2) + s2 * __expf(m2 - M2);
            sm[t] = M2;
        }
        __syncthreads();
    }
    if (t == 0) { gmax[b] = sm[0]; gsum[b] = ss[0]; }
}

__global__ void softmax_write(float* __restrict__ out,
                              const float* __restrict__ gmax, const float* __restrict__ gsum)
{
    int b = blockIdx.y;
    int i4 = blockIdx.x * blockDim.x + threadIdx.x;
    if (i4 * 4 >= NITEMS) return;
    float m = gmax[b], inv = 1.f / gsum[b];
    float4* p = (float4*)(out + (size_t)b * NITEMS) + i4;
    float4 v = *p;
    v.x = __expf(v.x - m) * inv; v.y = __expf(v.y - m) * inv;
    v.z = __expf(v.z - m) * inv; v.w = __expf(v.w - m) * inv;
    *p = v;
}

// ---------------- launcher ----------------
extern "C" void kernel_launch(void* const* d_in, const int* in_sizes, int n_in,
                              void* d_out, int out_size)
{
    const float* adj       = (const float*)d_in[0];
    const int*   items     = (const int*)  d_in[1];
    const int*   last_item = (const int*)  d_in[2];
    const int*   idx       = (const int*)  d_in[3];
    const float* emb       = (const float*)d_in[4];
    const float* W1  = (const float*)d_in[5];
    const float* b1  = (const float*)d_in[6];
    const float* W2  = (const float*)d_in[7];
    const float* b2  = (const float*)d_in[8];
    const float* Wf1 = (const float*)d_in[9];
    const float* bf1 = (const float*)d_in[10];
    const float* Wf2 = (const float*)d_in[11];
    const float* bf2 = (const float*)d_in[12];
    const float* Wf3 = (const float*)d_in[13];
    const float* Wf4 = (const float*)d_in[14];
    const float* bf4 = (const float*)d_in[15];
    float* out = (float*)d_out;

    float* fb = nullptr;
    cudaGetSymbolAddress((void**)&fb, g_f);
    float* h    = fb + F_H;
    float* z    = fb + F_Z;
    float* q2   = fb + F_Q2;
    float* part = fb + F_P;
    float* q1s  = fb + F_Q1S;
    float* sg   = fb + F_SG;
    float* w1t  = fb + F_W1T;
    float* w2t  = fb + F_W2T;
    float* wf1t = fb + F_WF1T;
    float* wf2t = fb + F_WF2T;
    float* wf4t = fb + F_WF4T;
    float* gmax = fb + F_MAX;
    float* gsum = fb + F_SUM;

    __nv_bfloat16 *adjh, *adjl, *embh, *embl, *xh, *xl, *shh, *shl;
    cudaGetSymbolAddress((void**)&adjh, g_adj_h);
    cudaGetSymbolAddress((void**)&adjl, g_adj_l);
    cudaGetSymbolAddress((void**)&embh, g_emb_h);
    cudaGetSymbolAddress((void**)&embl, g_emb_l);
    cudaGetSymbolAddress((void**)&xh,   g_x_h);
    cudaGetSymbolAddress((void**)&xl,   g_x_l);
    cudaGetSymbolAddress((void**)&shh,  g_sh_h);
    cudaGetSymbolAddress((void**)&shl,  g_sh_l);

    static bool inited = false;
    if (!inited) {
        cudaFuncSetAttribute(gemm_sp2, cudaFuncAttributeMaxDynamicSharedMemorySize, SP_SMEM);
        inited = true;
    }

    // launch 0: fused transposes
    transpose_all<<<dim3(16, 8, 5), dim3(32, 8)>>>(W1, W2, Wf1, Wf2, Wf4,
                                                   w1t, w2t, wf1t, wf2t, wf4t);
    // launch 1: zero sg
    zero_k<<<256, 256>>>(sg, BSESS * HID);
    // launch 2-3: input splits
    cvt_split<<<2048, 256>>>(adj, adjh, adjl, (size_t)NNODES * NNODES, (size_t)NNODES * NNODES);
    cvt_split<<<1024, 256>>>(emb, embh, embl, (size_t)NITEMS * HID, (size_t)NITEMS_PAD * HID);
    // launch 4: t1^T = (emb[items] @ W1^T + b1)^T, written directly as bf16 hi/lo
    gemm_tiled<<<dim3(2, 64), 256>>>(emb, HID, items, w1t, HID, b1,
                                     nullptr, xh, xl, NNODES, NNODES, HID, HID, 0, 1);
    // launch 5 (ncu capture target): h_part = adj @ t1, split-K x2
    gemm_sp2<<<dim3(1, 64, 2), 256, SP_SMEM>>>(adjh, adjl, NNODES, xh, xl, NNODES,
                                               part, HID, NH, HID, NNODES / 2);
    combine2<<<NH / 1024, 256>>>(part, h, 1);
    // t2^T split
    gemm_tiled<<<dim3(2, 64), 256>>>(h, HID, nullptr, w2t, HID, b2,
                                     nullptr, xh, xl, NNODES, NNODES, HID, HID, 0, 1);
    // z = adj @ t2
    gemm_sp2<<<dim3(1, 64, 2), 256, SP_SMEM>>>(adjh, adjl, NNODES, xh, xl, NNODES,
                                               part, HID, NH, HID, NNODES / 2);
    combine2<<<NH / 1024, 256>>>(part, z, 0);
    // q1s / q2 (fp32)
    gemm_tiled<<<dim3(2, 4), 256>>>(z, HID, last_item, wf1t, HID, bf1,
                                    q1s, nullptr, nullptr, HID, BSESS, HID, HID, 0, 0);
    gemm_tiled<<<dim3(2, 64), 256>>>(z, HID, nullptr, wf2t, HID, bf2,
                                     q2, nullptr, nullptr, HID, NNODES, HID, HID, 0, 0);
    alpha_scatter<<<NNODES, 256>>>(q1s, q2, z, Wf3, idx, sg);
    sh_kernel<<<BSESS, 256>>>(z, last_item, sg, wf4t, bf4, shh, shl);
    // logits: out[b][i] = sh[b,:] . emb[i,:]
    gemm_sp2<<<dim3(NITEMS_PAD / 256, BSESS / 128, 1), 256, SP_SMEM>>>(
        shh, shl, HID, embh, embl, HID, out, NITEMS, 0, NITEMS, HID);
    // softmax in place
    softmax_reduce<<<BSESS, 256>>>(out, gmax, gsum);
    softmax_write<<<dim3((NITEMS / 4 + 255) / 256, BSESS), 256>>>(out, gmax, gsum);
}

// round 11
// speedup vs baseline: 1.5479x; 1.5479x over previous
#include <cuda_runtime.h>
#include <cuda_bf16.h>
#include <math.h>
#include <stdint.h>

#define HID 256
#define NNODES 8192
#define BSESS 512
#define NITEMS 100000
#define NITEMS_PAD 100096           // 782 * 128

// ---------------- static scratch (floats) ----------------
constexpr size_t NH = (size_t)NNODES * HID;
constexpr size_t F_H    = 0;
constexpr size_t F_Z    = F_H   + NH;
constexpr size_t F_Q2   = F_Z   + NH;
constexpr size_t F_P    = F_Q2  + NH;                 // 2 x NH partials
constexpr size_t F_Q1S  = F_P   + 2 * NH;
constexpr size_t F_SG   = F_Q1S + (size_t)BSESS * HID;
constexpr size_t F_W1T  = F_SG  + (size_t)BSESS * HID;
constexpr size_t F_W2T  = F_W1T + (size_t)HID * HID;
constexpr size_t F_WF1T = F_W2T + (size_t)HID * HID;
constexpr size_t F_WF2T = F_WF1T + (size_t)HID * HID;
constexpr size_t F_WF4T = F_WF2T + (size_t)HID * HID;
constexpr size_t F_MAX  = F_WF4T + (size_t)2 * HID * HID;
constexpr size_t F_SUM  = F_MAX + BSESS;
constexpr size_t F_TOTAL = F_SUM + BSESS;
__device__ float g_f[F_TOTAL];

// bf16 hi/lo split buffers
__device__ __nv_bfloat16 g_adj_h[(size_t)NNODES * NNODES];
__device__ __nv_bfloat16 g_adj_l[(size_t)NNODES * NNODES];
__device__ __nv_bfloat16 g_emb_h[(size_t)NITEMS_PAD * HID];
__device__ __nv_bfloat16 g_emb_l[(size_t)NITEMS_PAD * HID];
__device__ __nv_bfloat16 g_x_h[(size_t)HID * NNODES];
__device__ __nv_bfloat16 g_x_l[(size_t)HID * NNODES];
__device__ __nv_bfloat16 g_sh_h[(size_t)BSESS * HID];
__device__ __nv_bfloat16 g_sh_l[(size_t)BSESS * HID];

// ---------------- PTX helpers ----------------
__device__ __forceinline__ uint32_t smem_u32(const void* p) {
    uint32_t a;
    asm("{ .reg .u64 t; cvta.to.shared.u64 t, %1; cvt.u32.u64 %0, t; }" : "=r"(a) : "l"(p));
    return a;
}
#define LDM_X4(r, a) \
    asm volatile("ldmatrix.sync.aligned.m8n8.x4.shared.b16 {%0,%1,%2,%3}, [%4];" \
        : "=r"((r)[0]), "=r"((r)[1]), "=r"((r)[2]), "=r"((r)[3]) : "r"(a))
#define MMA16816(c, a, b0, b1) \
    asm volatile("mma.sync.aligned.m16n8k16.row.col.f32.bf16.bf16.f32 " \
        "{%0,%1,%2,%3}, {%4,%5,%6,%7}, {%8,%9}, {%0,%1,%2,%3};" \
        : "+f"((c)[0]), "+f"((c)[1]), "+f"((c)[2]), "+f"((c)[3]) \
        : "r"((a)[0]), "r"((a)[1]), "r"((a)[2]), "r"((a)[3]), "r"(b0), "r"(b1))
#define CP_ASYNC16(dst, src) \
    asm volatile("cp.async.cg.shared.global [%0], [%1], 16;" :: "r"(dst), "l"(src) : "memory")
#define CP_COMMIT() asm volatile("cp.async.commit_group;" ::: "memory")
#define CP_WAIT1()  asm volatile("cp.async.wait_group 1;" ::: "memory")
#define CP_WAIT0()  asm volatile("cp.async.wait_group 0;" ::: "memory")

// ---------------- fp32 -> bf16 hi/lo split ----------------
__global__ void cvt_split(const float* __restrict__ src, __nv_bfloat16* __restrict__ hi,
                          __nv_bfloat16* __restrict__ lo, size_t nsrc, size_t ntot)
{
    size_t stride = (size_t)gridDim.x * blockDim.x;
    for (size_t t = (size_t)blockIdx.x * blockDim.x + threadIdx.x; t * 4 < ntot; t += stride) {
        size_t i = t * 4;
        float4 v = (i < nsrc) ? *(const float4*)(src + i) : make_float4(0.f, 0.f, 0.f, 0.f);
        float f[4] = {v.x, v.y, v.z, v.w};
        __nv_bfloat16 h[4], l[4];
        #pragma unroll
        for (int j = 0; j < 4; j++) {
            h[j] = __float2bfloat16_rn(f[j]);
            l[j] = __float2bfloat16_rn(f[j] - __bfloat162float(h[j]));
        }
        *(__nv_bfloat162*)(hi + i)     = __nv_bfloat162(h[0], h[1]);
        *(__nv_bfloat162*)(hi + i + 2) = __nv_bfloat162(h[2], h[3]);
        *(__nv_bfloat162*)(lo + i)     = __nv_bfloat162(l[0], l[1]);
        *(__nv_bfloat162*)(lo + i + 2) = __nv_bfloat162(l[2], l[3]);
    }
}

// ---------------- bf16-split GEMM, BM=128 x BN=128, BK=32, 2 stages, occ 2 ----------------
// C[m][n] (+ z*partStride) = A @ B^T, A=Ah+Al [M][K] rowmajor, B=Bh+Bl [N][K] rowmajor.
// 256 threads = 8 warps (2x4), warp tile 64x32. blockIdx.z = K-split part (kbase = z*K).
#define SP_PITCH 80
#define SP_AMAT  10240                 // 128 rows * 80 B
#define SP_STAGE 40960                 // 4 matrices (Ah, Al, Bh, Bl)
#define SP_SMEM  81920                 // 2 stages

__global__ __launch_bounds__(256, 2)
void gemm_sp(const __nv_bfloat16* __restrict__ Ah, const __nv_bfloat16* __restrict__ Al, int lda,
             const __nv_bfloat16* __restrict__ Bh, const __nv_bfloat16* __restrict__ Bl, int ldb,
             float* __restrict__ C, size_t ldc, size_t partStride, int Nbound, int K)
{
    extern __shared__ __align__(128) char smem[];
    uint32_t sbase = smem_u32(smem);
    int tid = threadIdx.x, wid = tid >> 5, lane = tid & 31;
    int n0 = blockIdx.x * 128;
    int m0 = blockIdx.y * 128;
    int kbase = blockIdx.z * K;
    int wm = (wid >> 2) * 64;
    int wn = (wid & 3) * 32;

    float acc[4][4][4];
    #pragma unroll
    for (int a = 0; a < 4; a++)
        #pragma unroll
        for (int b = 0; b < 4; b++)
            #pragma unroll
            for (int cc = 0; cc < 4; cc++) acc[a][b][cc] = 0.f;

    auto copy_stage = [&](int s, int k0e) {
        uint32_t dst0 = sbase + (uint32_t)s * SP_STAGE;
        int colb = kbase + k0e + (tid & 3) * 8;
        #pragma unroll
        for (int j = 0; j < 8; j++) {
            int c = j * 256 + tid;
            int mat = c >> 9;
            int row = (c >> 2) & 127;
            const __nv_bfloat16* g;
            if (mat == 0)      g = Ah + (size_t)(m0 + row) * lda + colb;
            else if (mat == 1) g = Al + (size_t)(m0 + row) * lda + colb;
            else if (mat == 2) g = Bh + (size_t)(n0 + row) * ldb + colb;
            else               g = Bl + (size_t)(n0 + row) * ldb + colb;
            uint32_t dst = dst0 + (uint32_t)mat * SP_AMAT + (uint32_t)row * SP_PITCH
                         + (uint32_t)(tid & 3) * 16;
            CP_ASYNC16(dst, g);
        }
    };

    int kt = K / 32;
    copy_stage(0, 0);
    CP_COMMIT();

    for (int ki = 0; ki < kt; ki++) {
        int s = ki & 1;
        if (ki + 1 < kt) {
            copy_stage(s ^ 1, (ki + 1) * 32);
            CP_COMMIT();
            CP_WAIT1();
        } else {
            CP_WAIT0();
        }
        __syncthreads();

        uint32_t As  = sbase + (uint32_t)s * SP_STAGE;
        uint32_t Asl = As + SP_AMAT;
        uint32_t Bs  = As + 2 * SP_AMAT;
        uint32_t Bsl = As + 3 * SP_AMAT;

        #pragma unroll
        for (int kb = 0; kb < 32; kb += 16) {
            uint32_t af[4][4], b1[2][4], b2[2][4];
            uint32_t aoff = (uint32_t)(wm + (lane & 15)) * SP_PITCH
                          + (uint32_t)(kb + ((lane >> 4) << 3)) * 2;
            uint32_t boff = (uint32_t)(wn + (lane & 7) + ((lane >> 1) & 8)) * SP_PITCH
                          + (uint32_t)(kb + ((lane >> 3) & 1) * 8) * 2;
            // term 1: Ah * Bh
            #pragma unroll
            for (int mt = 0; mt < 4; mt++) LDM_X4(af[mt], As + aoff + mt * 16 * SP_PITCH);
            #pragma unroll
            for (int p = 0; p < 2; p++)    LDM_X4(b1[p], Bs + boff + p * 16 * SP_PITCH);
            #pragma unroll
            for (int mt = 0; mt < 4; mt++)
                #pragma unroll
                for (int nt = 0; nt < 4; nt++) {
                    int p = nt >> 1, q = (nt & 1) * 2;
                    MMA16816(acc[mt][nt], af[mt], b1[p][q], b1[p][q + 1]);
                }
            // term 2: Ah * Bl
            #pragma unroll
            for (int p = 0; p < 2; p++)    LDM_X4(b2[p], Bsl + boff + p * 16 * SP_PITCH);
            #pragma unroll
            for (int mt = 0; mt < 4; mt++)
                #pragma unroll
                for (int nt = 0; nt < 4; nt++) {
                    int p = nt >> 1, q = (nt & 1) * 2;
                    MMA16816(acc[mt][nt], af[mt], b2[p][q], b2[p][q + 1]);
                }
            // term 3: Al * Bh (overwrite A frags)
            #pragma unroll
            for (int mt = 0; mt < 4; mt++) LDM_X4(af[mt], Asl + aoff + mt * 16 * SP_PITCH);
            #pragma unroll
            for (int mt = 0; mt < 4; mt++)
                #pragma unroll
                for (int nt = 0; nt < 4; nt++) {
                    int p = nt >> 1, q = (nt & 1) * 2;
                    MMA16816(acc[mt][nt], af[mt], b1[p][q], b1[p][q + 1]);
                }
        }
        __syncthreads();
    }

    float* Cp = C + (size_t)blockIdx.z * partStride;
    #pragma unroll
    for (int mt = 0; mt < 4; mt++)
        #pragma unroll
        for (int nt = 0; nt < 4; nt++) {
            int m = m0 + wm + mt * 16 + (lane >> 2);
            int n = n0 + wn + nt * 8 + (lane & 3) * 2;
            if (n < Nbound) {
                *(float2*)&Cp[(size_t)m * ldc + n] = make_float2(acc[mt][nt][0], acc[mt][nt][1]);
                *(float2*)&Cp[(size_t)(m + 8) * ldc + n] = make_float2(acc[mt][nt][2], acc[mt][nt][3]);
            }
        }
}

// combine split-K partials: o = op(p[i] + p[i+NH])
__global__ void combine2(const float* __restrict__ p, float* __restrict__ o, int doRelu)
{
    size_t i = (size_t)blockIdx.x * blockDim.x + threadIdx.x;
    const float4* a = (const float4*)p;
    size_t s = NH / 4;
    float4 v0 = a[i], v1 = a[i + s];
    float4 v = make_float4(v0.x + v1.x, v0.y + v1.y, v0.z + v1.z, v0.w + v1.w);
    if (doRelu) {
        v.x = fmaxf(v.x, 0.f); v.y = fmaxf(v.y, 0.f);
        v.z = fmaxf(v.z, 0.f); v.w = fmaxf(v.w, 0.f);
    }
    ((float4*)o)[i] = v;
}

// ---------------- fused transpose of the 5 weight matrices ----------------
__global__ void transpose_all(const float* __restrict__ W1, const float* __restrict__ W2,
                              const float* __restrict__ Wf1, const float* __restrict__ Wf2,
                              const float* __restrict__ Wf4,
                              float* __restrict__ o1, float* __restrict__ o2,
                              float* __restrict__ o3, float* __restrict__ o4,
                              float* __restrict__ o5)
{
    int zid = blockIdx.z;
    const float* W = (zid == 0) ? W1 : (zid == 1) ? W2 : (zid == 2) ? Wf1 : (zid == 3) ? Wf2 : Wf4;
    float* Wt      = (zid == 0) ? o1 : (zid == 1) ? o2 : (zid == 2) ? o3 : (zid == 3) ? o4 : o5;
    int R = HID, C = (zid == 4) ? 2 * HID : HID;
    __shared__ float tile[32][33];
    int c0 = blockIdx.x * 32, r0 = blockIdx.y * 32;
    if (c0 >= C) return;
    int x = threadIdx.x, y = threadIdx.y;
    #pragma unroll
    for (int dy = 0; dy < 32; dy += 8) {
        int r = r0 + y + dy, c = c0 + x;
        if (r < R && c < C) tile[y + dy][x] = W[(size_t)r * C + c];
    }
    __syncthreads();
    #pragma unroll
    for (int dy = 0; dy < 32; dy += 8) {
        int c = c0 + y + dy, r = r0 + x;
        if (c < C && r < R) Wt[(size_t)c * R + r] = tile[x][y + dy];
    }
}

// ---------------- fp32 tiled GEMM (small GEMMs; optional split-bf16 transC output) ----------------
#define BM 128
#define BN 128
#define BK 16
__global__ __launch_bounds__(256)
void gemm_tiled(const float* __restrict__ A, int lda, const int* __restrict__ gidx,
                const float* __restrict__ B, int ldb, const float* __restrict__ bias,
                float* __restrict__ C, __nv_bfloat16* __restrict__ hiC, __nv_bfloat16* __restrict__ loC,
                int ldc, int M, int N, int K, int doRelu, int transC)
{
    __shared__ __align__(16) float As[BK][BM];
    __shared__ __align__(16) float Bs[BK][BN];
    int tid = threadIdx.x;
    int tx = tid & 15, ty = tid >> 4;
    int m0 = blockIdx.y * BM, n0 = blockIdx.x * BN;
    int ai = transC ? tx : ty, bi = transC ? ty : tx;
    int ai4 = ai * 4, bi4 = bi * 4;
    float acc[8][8];
    #pragma unroll
    for (int i = 0; i < 8; i++)
        #pragma unroll
        for (int j = 0; j < 8; j++) acc[i][j] = 0.f;
    int arow = tid >> 2, acol = (tid & 3) * 4;
    int r0i = m0 + arow, r1i = m0 + arow + 64;
    bool v0 = r0i < M, v1 = r1i < M;
    int gr0 = r0i, gr1 = r1i;
    if (gidx) { if (v0) gr0 = gidx[r0i]; if (v1) gr1 = gidx[r1i]; }
    const float* Arow0 = A + (size_t)gr0 * lda;
    const float* Arow1 = A + (size_t)gr1 * lda;
    int brow = tid >> 5, bcol = (tid & 31) * 4;
    for (int k0 = 0; k0 < K; k0 += BK) {
        float4 a0 = v0 ? *(const float4*)(Arow0 + k0 + acol) : make_float4(0, 0, 0, 0);
        float4 a1 = v1 ? *(const float4*)(Arow1 + k0 + acol) : make_float4(0, 0, 0, 0);
        float4 b0 = *(const float4*)(B + (size_t)(k0 + brow) * ldb + n0 + bcol);
        float4 b1 = *(const float4*)(B + (size_t)(k0 + brow + 8) * ldb + n0 + bcol);
        As[acol + 0][arow] = a0.x; As[acol + 1][arow] = a0.y;
        As[acol + 2][arow] = a0.z; As[acol + 3][arow] = a0.w;
        As[acol + 0][arow + 64] = a1.x; As[acol + 1][arow + 64] = a1.y;
        As[acol + 2][arow + 64] = a1.z; As[acol + 3][arow + 64] = a1.w;
        *(float4*)&Bs[brow][bcol] = b0;
        *(float4*)&Bs[brow + 8][bcol] = b1;
        __syncthreads();
        #pragma unroll
        for (int k = 0; k < BK; k++) {
            float4 aa0 = *(const float4*)&As[k][ai4];
            float4 aa1 = *(const float4*)&As[k][64 + ai4];
            float4 bb0 = *(const float4*)&Bs[k][bi4];
            float4 bb1 = *(const float4*)&Bs[k][64 + bi4];
            float af[8] = {aa0.x, aa0.y, aa0.z, aa0.w, aa1.x, aa1.y, aa1.z, aa1.w};
            float bf[8] = {bb0.x, bb0.y, bb0.z, bb0.w, bb1.x, bb1.y, bb1.z, bb1.w};
            #pragma unroll
            for (int i = 0; i < 8; i++)
                #pragma unroll
                for (int j = 0; j < 8; j++) acc[i][j] += af[i] * bf[j];
        }
        __syncthreads();
    }
    if (!transC) {
        #pragma unroll
        for (int i8 = 0; i8 < 8; i8++) {
            int m = m0 + ((i8 < 4) ? (ai4 + i8) : (64 + ai4 + i8 - 4));
            if (m >= M) continue;
            #pragma unroll
            for (int jg = 0; jg < 2; jg++) {
                int n = n0 + jg * 64 + bi4;
                float4 v = make_float4(acc[i8][jg*4], acc[i8][jg*4+1], acc[i8][jg*4+2], acc[i8][jg*4+3]);
                if (bias) { v.x += bias[n]; v.y += bias[n+1]; v.z += bias[n+2]; v.w += bias[n+3]; }
                if (doRelu) { v.x = fmaxf(v.x, 0.f); v.y = fmaxf(v.y, 0.f); v.z = fmaxf(v.z, 0.f); v.w = fmaxf(v.w, 0.f); }
                *(float4*)&C[(size_t)m * ldc + n] = v;
            }
        }
    } else {
        #pragma unroll
        for (int j8 = 0; j8 < 8; j8++) {
            int n = n0 + ((j8 < 4) ? (bi4 + j8) : (64 + bi4 + j8 - 4));
            float bv = bias ? bias[n] : 0.f;
            #pragma unroll
            for (int ig = 0; ig < 2; ig++) {
                int m = m0 + ig * 64 + ai4;
                if (m >= M) continue;
                float v[4] = {acc[ig*4][j8]+bv, acc[ig*4+1][j8]+bv, acc[ig*4+2][j8]+bv, acc[ig*4+3][j8]+bv};
                if (hiC) {
                    __nv_bfloat16 hh[4], ll[4];
                    #pragma unroll
                    for (int q = 0; q < 4; q++) {
                        hh[q] = __float2bfloat16_rn(v[q]);
                        ll[q] = __float2bfloat16_rn(v[q] - __bfloat162float(hh[q]));
                    }
                    size_t off = (size_t)n * ldc + m;
                    *(__nv_bfloat162*)(hiC + off)     = __nv_bfloat162(hh[0], hh[1]);
                    *(__nv_bfloat162*)(hiC + off + 2) = __nv_bfloat162(hh[2], hh[3]);
                    *(__nv_bfloat162*)(loC + off)     = __nv_bfloat162(ll[0], ll[1]);
                    *(__nv_bfloat162*)(loC + off + 2) = __nv_bfloat162(ll[2], ll[3]);
                } else {
                    *(float4*)&C[(size_t)n * ldc + m] = make_float4(v[0], v[1], v[2], v[3]);
                }
            }
        }
    }
}

__global__ void zero_k(float* p, int n)
{
    for (int i = blockIdx.x * blockDim.x + threadIdx.x; i < n; i += gridDim.x * blockDim.x)
        p[i] = 0.f;
}

// ---------------- attention / pooling / softmax ----------------
__global__ void alpha_scatter(const float* __restrict__ q1s, const float* __restrict__ q2,
                              const float* __restrict__ z, const float* __restrict__ Wf3,
                              const int* __restrict__ idx, float* __restrict__ sg)
{
    int n = blockIdx.x, c = threadIdx.x;
    int b = idx[n];
    float q = q1s[b * HID + c] + q2[(size_t)n * HID + c];
    float t = Wf3[c] / (1.f + __expf(-q));
    #pragma unroll
    for (int o = 16; o > 0; o >>= 1) t += __shfl_xor_sync(0xffffffffu, t, o);
    __shared__ float red[8];
    if ((c & 31) == 0) red[c >> 5] = t;
    __syncthreads();
    float alpha = red[0] + red[1] + red[2] + red[3] + red[4] + red[5] + red[6] + red[7];
    atomicAdd(&sg[b * HID + c], alpha * z[(size_t)n * HID + c]);
}

__global__ void sh_kernel(const float* __restrict__ z, const int* __restrict__ last_item,
                          const float* __restrict__ sg, const float* __restrict__ wf4t,
                          const float* __restrict__ bf4,
                          __nv_bfloat16* __restrict__ shh, __nv_bfloat16* __restrict__ shl)
{
    int b = blockIdx.x, c = threadIdx.x;
    __shared__ float srow[2 * HID];
    int li = last_item[b];
    srow[c]       = z[(size_t)li * HID + c];
    srow[HID + c] = sg[b * HID + c];
    __syncthreads();
    float acc = bf4[c];
    #pragma unroll 8
    for (int k = 0; k < 2 * HID; k++) acc += srow[k] * wf4t[k * HID + c];
    __nv_bfloat16 hh = __float2bfloat16_rn(acc);
    shh[b * HID + c] = hh;
    shl[b * HID + c] = __float2bfloat16_rn(acc - __bfloat162float(hh));
}

__global__ void softmax_reduce(const float* __restrict__ out,
                               float* __restrict__ gmax, float* __restrict__ gsum)
{
    int b = blockIdx.x, t = threadIdx.x;
    const float* row = out + (size_t)b * NITEMS;
    float m = -1e30f, s = 0.f;
    for (int i = t; i < NITEMS; i += 256) {
        float v = row[i];
        if (v > m) { s = s * __expf(m - v) + 1.f; m = v; }
        else       { s += __expf(v - m); }
    }
    __shared__ float sm[256], ss[256];
    sm[t] = m; ss[t] = s;
    __syncthreads();
    for (int o = 128; o > 0; o >>= 1) {
        if (t < o) {
            float m2 = sm[t + o], s2 = ss[t + o];
            float M2 = fmaxf(sm[t], m2);
            ss[t] = ss[t] * __expf(sm[t] - M2) + s2 * __expf(m2 - M2);
            sm[t] = M2;
        }
        __syncthreads();
    }
    if (t == 0) { gmax[b] = sm[0]; gsum[b] = ss[0]; }
}

__global__ void softmax_write(float* __restrict__ out,
                              const float* __restrict__ gmax, const float* __restrict__ gsum)
{
    int b = blockIdx.y;
    int i4 = blockIdx.x * blockDim.x + threadIdx.x;
    if (i4 * 4 >= NITEMS) return;
    float m = gmax[b], inv = 1.f / gsum[b];
    float4* p = (float4*)(out + (size_t)b * NITEMS) + i4;
    float4 v = *p;
    v.x = __expf(v.x - m) * inv; v.y = __expf(v.y - m) * inv;
    v.z = __expf(v.z - m) * inv; v.w = __expf(v.w - m) * inv;
    *p = v;
}

// ---------------- launcher ----------------
extern "C" void kernel_launch(void* const* d_in, const int* in_sizes, int n_in,
                              void* d_out, int out_size)
{
    const float* adj       = (const float*)d_in[0];
    const int*   items     = (const int*)  d_in[1];
    const int*   last_item = (const int*)  d_in[2];
    const int*   idx       = (const int*)  d_in[3];
    const float* emb       = (const float*)d_in[4];
    const float* W1  = (const float*)d_in[5];
    const float* b1  = (const float*)d_in[6];
    const float* W2  = (const float*)d_in[7];
    const float* b2  = (const float*)d_in[8];
    const float* Wf1 = (const float*)d_in[9];
    const float* bf1 = (const float*)d_in[10];
    const float* Wf2 = (const float*)d_in[11];
    const float* bf2 = (const float*)d_in[12];
    const float* Wf3 = (const float*)d_in[13];
    const float* Wf4 = (const float*)d_in[14];
    const float* bf4 = (const float*)d_in[15];
    float* out = (float*)d_out;

    float* fb = nullptr;
    cudaGetSymbolAddress((void**)&fb, g_f);
    float* h    = fb + F_H;
    float* z    = fb + F_Z;
    float* q2   = fb + F_Q2;
    float* part = fb + F_P;
    float* q1s  = fb + F_Q1S;
    float* sg   = fb + F_SG;
    float* w1t  = fb + F_W1T;
    float* w2t  = fb + F_W2T;
    float* wf1t = fb + F_WF1T;
    float* wf2t = fb + F_WF2T;
    float* wf4t = fb + F_WF4T;
    float* gmax = fb + F_MAX;
    float* gsum = fb + F_SUM;

    __nv_bfloat16 *adjh, *adjl, *embh, *embl, *xh, *xl, *shh, *shl;
    cudaGetSymbolAddress((void**)&adjh, g_adj_h);
    cudaGetSymbolAddress((void**)&adjl, g_adj_l);
    cudaGetSymbolAddress((void**)&embh, g_emb_h);
    cudaGetSymbolAddress((void**)&embl, g_emb_l);
    cudaGetSymbolAddress((void**)&xh,   g_x_h);
    cudaGetSymbolAddress((void**)&xl,   g_x_l);
    cudaGetSymbolAddress((void**)&shh,  g_sh_h);
    cudaGetSymbolAddress((void**)&shl,  g_sh_l);

    static bool inited = false;
    if (!inited) {
        cudaFuncSetAttribute(gemm_sp, cudaFuncAttributeMaxDynamicSharedMemorySize, SP_SMEM);
        inited = true;
    }

    transpose_all<<<dim3(16, 8, 5), dim3(32, 8)>>>(W1, W2, Wf1, Wf2, Wf4,
                                                   w1t, w2t, wf1t, wf2t, wf4t);
    zero_k<<<256, 256>>>(sg, BSESS * HID);
    cvt_split<<<2048, 256>>>(adj, adjh, adjl, (size_t)NNODES * NNODES, (size_t)NNODES * NNODES);
    cvt_split<<<1024, 256>>>(emb, embh, embl, (size_t)NITEMS * HID, (size_t)NITEMS_PAD * HID);
    // t1^T = (emb[items] @ W1^T + b1)^T, written directly as bf16 hi/lo [256][8192]
    gemm_tiled<<<dim3(2, 64), 256>>>(emb, HID, items, w1t, HID, b1,
                                     nullptr, xh, xl, NNODES, NNODES, HID, HID, 0, 1);
    // h = relu(adj @ t1): split-K x2 + combine  (grid x=2 covers all 256 N columns!)
    gemm_sp<<<dim3(2, 64, 2), 256, SP_SMEM>>>(adjh, adjl, NNODES, xh, xl, NNODES,
                                              part, HID, NH, HID, NNODES / 2);
    combine2<<<NH / 1024, 256>>>(part, h, 1);
    // t2^T split
    gemm_tiled<<<dim3(2, 64), 256>>>(h, HID, nullptr, w2t, HID, b2,
                                     nullptr, xh, xl, NNODES, NNODES, HID, HID, 0, 1);
    // z = adj @ t2
    gemm_sp<<<dim3(2, 64, 2), 256, SP_SMEM>>>(adjh, adjl, NNODES, xh, xl, NNODES,
                                              part, HID, NH, HID, NNODES / 2);
    combine2<<<NH / 1024, 256>>>(part, z, 0);
    // q1s / q2 (fp32)
    gemm_tiled<<<dim3(2, 4), 256>>>(z, HID, last_item, wf1t, HID, bf1,
                                    q1s, nullptr, nullptr, HID, BSESS, HID, HID, 0, 0);
    gemm_tiled<<<dim3(2, 64), 256>>>(z, HID, nullptr, wf2t, HID, bf2,
                                     q2, nullptr, nullptr, HID, NNODES, HID, HID, 0, 0);
    alpha_scatter<<<NNODES, 256>>>(q1s, q2, z, Wf3, idx, sg);
    sh_kernel<<<BSESS, 256>>>(z, last_item, sg, wf4t, bf4, shh, shl);
    // logits: out[b][i] = sh[b,:] . emb[i,:]
    gemm_sp<<<dim3(NITEMS_PAD / 128, BSESS / 128, 1), 256, SP_SMEM>>>(
        shh, shl, HID, embh, embl, HID, out, NITEMS, 0, NITEMS, HID);
    // softmax in place
    softmax_reduce<<<BSESS, 256>>>(out, gmax, gsum);
    softmax_write<<<dim3((NITEMS / 4 + 255) / 256, BSESS), 256>>>(out, gmax, gsum);
}

// round 13
// speedup vs baseline: 1.6642x; 1.0751x over previous
#include <cuda_runtime.h>
#include <cuda_bf16.h>
#include <math.h>
#include <stdint.h>

#define HID 256
#define NNODES 8192
#define BSESS 512
#define NITEMS 100000
#define NITEMS_PAD 100096           // 782 * 128
#define LG_GX 782

// ---------------- static scratch (floats) ----------------
constexpr size_t NH = (size_t)NNODES * HID;
constexpr size_t F_Z    = 0;
constexpr size_t F_Q2   = F_Z   + NH;
constexpr size_t F_P    = F_Q2  + NH;                 // 2 x NH partials (also softmax partials)
constexpr size_t F_Q1S  = F_P   + 2 * NH;
constexpr size_t F_SG   = F_Q1S + (size_t)BSESS * HID;
constexpr size_t F_WF4T = F_SG  + (size_t)BSESS * HID;
constexpr size_t F_MAX  = F_WF4T + (size_t)2 * HID * HID;
constexpr size_t F_SUM  = F_MAX + BSESS;
constexpr size_t F_TOTAL = F_SUM + BSESS;
__device__ float g_f[F_TOTAL];

// bf16 hi/lo split buffers
__device__ __nv_bfloat16 g_adj_h[(size_t)NNODES * NNODES];
__device__ __nv_bfloat16 g_adj_l[(size_t)NNODES * NNODES];
__device__ __nv_bfloat16 g_emb_h[(size_t)NITEMS_PAD * HID];
__device__ __nv_bfloat16 g_emb_l[(size_t)NITEMS_PAD * HID];
__device__ __nv_bfloat16 g_x_h[(size_t)HID * NNODES];
__device__ __nv_bfloat16 g_x_l[(size_t)HID * NNODES];
__device__ __nv_bfloat16 g_h_h[NH], g_h_l[NH];
__device__ __nv_bfloat16 g_z_h[NH], g_z_l[NH];
__device__ __nv_bfloat16 g_sh_h[(size_t)BSESS * HID];
__device__ __nv_bfloat16 g_sh_l[(size_t)BSESS * HID];
__device__ __nv_bfloat16 g_w1h[65536], g_w1l[65536];
__device__ __nv_bfloat16 g_w2h[65536], g_w2l[65536];
__device__ __nv_bfloat16 g_wf1h[65536], g_wf1l[65536];
__device__ __nv_bfloat16 g_wf2h[65536], g_wf2l[65536];

// ---------------- PTX helpers ----------------
__device__ __forceinline__ uint32_t smem_u32(const void* p) {
    uint32_t a;
    asm("{ .reg .u64 t; cvta.to.shared.u64 t, %1; cvt.u32.u64 %0, t; }" : "=r"(a) : "l"(p));
    return a;
}
#define LDM_X4(r, a) \
    asm volatile("ldmatrix.sync.aligned.m8n8.x4.shared.b16 {%0,%1,%2,%3}, [%4];" \
        : "=r"((r)[0]), "=r"((r)[1]), "=r"((r)[2]), "=r"((r)[3]) : "r"(a))
#define MMA16816(c, a, b0, b1) \
    asm volatile("mma.sync.aligned.m16n8k16.row.col.f32.bf16.bf16.f32 " \
        "{%0,%1,%2,%3}, {%4,%5,%6,%7}, {%8,%9}, {%0,%1,%2,%3};" \
        : "+f"((c)[0]), "+f"((c)[1]), "+f"((c)[2]), "+f"((c)[3]) \
        : "r"((a)[0]), "r"((a)[1]), "r"((a)[2]), "r"((a)[3]), "r"(b0), "r"(b1))
#define CP_ASYNC16(dst, src) \
    asm volatile("cp.async.cg.shared.global [%0], [%1], 16;" :: "r"(dst), "l"(src) : "memory")
#define CP_COMMIT() asm volatile("cp.async.commit_group;" ::: "memory")
#define CP_WAIT1()  asm volatile("cp.async.wait_group 1;" ::: "memory")
#define CP_WAIT0()  asm volatile("cp.async.wait_group 0;" ::: "memory")

__device__ __forceinline__ uint32_t fkey(float f) {
    uint32_t u = __float_as_uint(f);
    return (u & 0x80000000u) ? ~u : (u | 0x80000000u);
}
__device__ __forceinline__ float funkey(uint32_t k) {
    uint32_t u = (k & 0x80000000u) ? (k & 0x7fffffffu) : ~k;
    return __uint_as_float(u);
}

// ---------------- fp32 -> bf16 hi/lo split ----------------
__global__ void cvt_split(const float* __restrict__ src, __nv_bfloat16* __restrict__ hi,
                          __nv_bfloat16* __restrict__ lo, size_t nsrc, size_t ntot)
{
    size_t stride = (size_t)gridDim.x * blockDim.x;
    for (size_t t = (size_t)blockIdx.x * blockDim.x + threadIdx.x; t * 4 < ntot; t += stride) {
        size_t i = t * 4;
        float4 v = (i < nsrc) ? *(const float4*)(src + i) : make_float4(0.f, 0.f, 0.f, 0.f);
        float f[4] = {v.x, v.y, v.z, v.w};
        __nv_bfloat16 h[4], l[4];
        #pragma unroll
        for (int j = 0; j < 4; j++) {
            h[j] = __float2bfloat16_rn(f[j]);
            l[j] = __float2bfloat16_rn(f[j] - __bfloat162float(h[j]));
        }
        *(__nv_bfloat162*)(hi + i)     = __nv_bfloat162(h[0], h[1]);
        *(__nv_bfloat162*)(hi + i + 2) = __nv_bfloat162(h[2], h[3]);
        *(__nv_bfloat162*)(lo + i)     = __nv_bfloat162(l[0], l[1]);
        *(__nv_bfloat162*)(lo + i + 2) = __nv_bfloat162(l[2], l[3]);
    }
}

// ---------------- bf16-split GEMM, BM=128 x BN=128, BK=32, 2 stages, occ 2 ----------------
// C = A @ B^T (3-term emulated fp32). A rows optionally gathered via gidxA, B via gidxB.
// Output: fp32 C (+blockIdx.z*partStride), or split bf16 (hiC/loC). Optional biasM[m]/biasN[n].
// partials != null: per-CTA per-row softmax (max, expsum) partials (layout [m][gridX] + offset).
#define SP_PITCH 80
#define SP_AMAT  10240
#define SP_STAGE 40960
#define SP_SMEM  81920

__global__ __launch_bounds__(256, 2)
void gemm_sp(const __nv_bfloat16* __restrict__ Ah, const __nv_bfloat16* __restrict__ Al,
             int lda, const int* __restrict__ gidxA,
             const __nv_bfloat16* __restrict__ Bh, const __nv_bfloat16* __restrict__ Bl,
             int ldb, const int* __restrict__ gidxB,
             float* __restrict__ C, __nv_bfloat16* __restrict__ hiC, __nv_bfloat16* __restrict__ loC,
             size_t ldc, size_t partStride,
             const float* __restrict__ biasM, const float* __restrict__ biasN,
             float* __restrict__ partials, int Nbound, int K)
{
    extern __shared__ __align__(128) char smem[];
    uint32_t sbase = smem_u32(smem);
    int tid = threadIdx.x, wid = tid >> 5, lane = tid & 31;
    int n0 = blockIdx.x * 128;
    int m0 = blockIdx.y * 128;
    int kbase = blockIdx.z * K;
    int wm = (wid >> 2) * 64;
    int wn = (wid & 3) * 32;

    float acc[4][4][4];
    #pragma unroll
    for (int a = 0; a < 4; a++)
        #pragma unroll
        for (int b = 0; b < 4; b++)
            #pragma unroll
            for (int cc = 0; cc < 4; cc++) acc[a][b][cc] = 0.f;

    auto copy_stage = [&](int s, int k0e) {
        uint32_t dst0 = sbase + (uint32_t)s * SP_STAGE;
        int colb = kbase + k0e + (tid & 3) * 8;
        #pragma unroll
        for (int j = 0; j < 8; j++) {
            int c = j * 256 + tid;
            int mat = c >> 9;
            int row = (c >> 2) & 127;
            const __nv_bfloat16* g;
            if (mat < 2) {
                int r = m0 + row;
                if (gidxA) r = gidxA[r];
                g = (mat ? Al : Ah) + (size_t)r * lda + colb;
            } else {
                int r = n0 + row;
                if (gidxB) r = gidxB[r];
                g = ((mat == 3) ? Bl : Bh) + (size_t)r * ldb + colb;
            }
            uint32_t dst = dst0 + (uint32_t)mat * SP_AMAT + (uint32_t)row * SP_PITCH
                         + (uint32_t)(tid & 3) * 16;
            CP_ASYNC16(dst, g);
        }
    };

    int kt = K / 32;
    copy_stage(0, 0);
    CP_COMMIT();

    for (int ki = 0; ki < kt; ki++) {
        int s = ki & 1;
        if (ki + 1 < kt) {
            copy_stage(s ^ 1, (ki + 1) * 32);
            CP_COMMIT();
            CP_WAIT1();
        } else {
            CP_WAIT0();
        }
        __syncthreads();

        uint32_t As  = sbase + (uint32_t)s * SP_STAGE;
        uint32_t Asl = As + SP_AMAT;
        uint32_t Bs  = As + 2 * SP_AMAT;
        uint32_t Bsl = As + 3 * SP_AMAT;

        #pragma unroll
        for (int kb = 0; kb < 32; kb += 16) {
            uint32_t af[4][4], b1[2][4], b2[2][4];
            uint32_t aoff = (uint32_t)(wm + (lane & 15)) * SP_PITCH
                          + (uint32_t)(kb + ((lane >> 4) << 3)) * 2;
            uint32_t boff = (uint32_t)(wn + (lane & 7) + ((lane >> 1) & 8)) * SP_PITCH
                          + (uint32_t)(kb + ((lane >> 3) & 1) * 8) * 2;
            #pragma unroll
            for (int mt = 0; mt < 4; mt++) LDM_X4(af[mt], As + aoff + mt * 16 * SP_PITCH);
            #pragma unroll
            for (int p = 0; p < 2; p++)    LDM_X4(b1[p], Bs + boff + p * 16 * SP_PITCH);
            #pragma unroll
            for (int mt = 0; mt < 4; mt++)
                #pragma unroll
                for (int nt = 0; nt < 4; nt++) {
                    int p = nt >> 1, q = (nt & 1) * 2;
                    MMA16816(acc[mt][nt], af[mt], b1[p][q], b1[p][q + 1]);
                }
            #pragma unroll
            for (int p = 0; p < 2; p++)    LDM_X4(b2[p], Bsl + boff + p * 16 * SP_PITCH);
            #pragma unroll
            for (int mt = 0; mt < 4; mt++)
                #pragma unroll
                for (int nt = 0; nt < 4; nt++) {
                    int p = nt >> 1, q = (nt & 1) * 2;
                    MMA16816(acc[mt][nt], af[mt], b2[p][q], b2[p][q + 1]);
                }
            #pragma unroll
            for (int mt = 0; mt < 4; mt++) LDM_X4(af[mt], Asl + aoff + mt * 16 * SP_PITCH);
            #pragma unroll
            for (int mt = 0; mt < 4; mt++)
                #pragma unroll
                for (int nt = 0; nt < 4; nt++) {
                    int p = nt >> 1, q = (nt & 1) * 2;
                    MMA16816(acc[mt][nt], af[mt], b1[p][q], b1[p][q + 1]);
                }
        }
        __syncthreads();
    }

    // -------- epilogue --------
    #pragma unroll
    for (int mt = 0; mt < 4; mt++)
        #pragma unroll
        for (int nt = 0; nt < 4; nt++) {
            int m = m0 + wm + mt * 16 + (lane >> 2);
            int n = n0 + wn + nt * 8 + (lane & 3) * 2;
            if (n >= Nbound) continue;
            float bm0 = biasM ? biasM[m] : 0.f;
            float bm1 = biasM ? biasM[m + 8] : 0.f;
            float bn0 = biasN ? biasN[n] : 0.f;
            float bn1 = biasN ? biasN[n + 1] : 0.f;
            float v0 = acc[mt][nt][0] + bm0 + bn0;
            float v1 = acc[mt][nt][1] + bm0 + bn1;
            float v2 = acc[mt][nt][2] + bm1 + bn0;
            float v3 = acc[mt][nt][3] + bm1 + bn1;
            if (hiC) {
                __nv_bfloat16 h0 = __float2bfloat16_rn(v0), h1 = __float2bfloat16_rn(v1);
                __nv_bfloat16 h2 = __float2bfloat16_rn(v2), h3 = __float2bfloat16_rn(v3);
                size_t o0 = (size_t)m * ldc + n, o1 = (size_t)(m + 8) * ldc + n;
                *(__nv_bfloat162*)(hiC + o0) = __nv_bfloat162(h0, h1);
                *(__nv_bfloat162*)(hiC + o1) = __nv_bfloat162(h2, h3);
                *(__nv_bfloat162*)(loC + o0) = __nv_bfloat162(
                    __float2bfloat16_rn(v0 - __bfloat162float(h0)),
                    __float2bfloat16_rn(v1 - __bfloat162float(h1)));
                *(__nv_bfloat162*)(loC + o1) = __nv_bfloat162(
                    __float2bfloat16_rn(v2 - __bfloat162float(h2)),
                    __float2bfloat16_rn(v3 - __bfloat162float(h3)));
            } else {
                float* Cp = C + (size_t)blockIdx.z * partStride;
                *(float2*)&Cp[(size_t)m * ldc + n]       = make_float2(v0, v1);
                *(float2*)&Cp[(size_t)(m + 8) * ldc + n] = make_float2(v2, v3);
            }
        }

    if (partials) {
        uint32_t* smax = (uint32_t*)smem;
        float* ssum = (float*)(smem + 512);
        if (tid < 128) { smax[tid] = fkey(-1e30f); ssum[tid] = 0.f; }
        __syncthreads();
        #pragma unroll
        for (int mt = 0; mt < 4; mt++)
            #pragma unroll
            for (int half = 0; half < 2; half++) {
                int rl = wm + mt * 16 + (lane >> 2) + half * 8;
                float vm = -1e30f;
                #pragma unroll
                for (int nt = 0; nt < 4; nt++) {
                    int n = n0 + wn + nt * 8 + (lane & 3) * 2;
                    if (n < Nbound)     vm = fmaxf(vm, acc[mt][nt][half * 2]);
                    if (n + 1 < Nbound) vm = fmaxf(vm, acc[mt][nt][half * 2 + 1]);
                }
                atomicMax(&smax[rl], fkey(vm));
            }
        __syncthreads();
        #pragma unroll
        for (int mt = 0; mt < 4; mt++)
            #pragma unroll
            for (int half = 0; half < 2; half++) {
                int rl = wm + mt * 16 + (lane >> 2) + half * 8;
                float rm = funkey(smax[rl]);
                float s = 0.f;
                #pragma unroll
                for (int nt = 0; nt < 4; nt++) {
                    int n = n0 + wn + nt * 8 + (lane & 3) * 2;
                    if (n < Nbound)     s += __expf(acc[mt][nt][half * 2] - rm);
                    if (n + 1 < Nbound) s += __expf(acc[mt][nt][half * 2 + 1] - rm);
                }
                atomicAdd(&ssum[rl], s);
            }
        __syncthreads();
        if (tid < 128) {
            size_t gx = gridDim.x;
            size_t rows = (size_t)gridDim.y * 128;
            partials[(size_t)(m0 + tid) * gx + blockIdx.x] = funkey(smax[tid]);
            partials[rows * gx + (size_t)(m0 + tid) * gx + blockIdx.x] = ssum[tid];
        }
    }
}

// combine split-K partials: fp32 and/or split bf16 output
__global__ void combine2(const float* __restrict__ p, float* __restrict__ oF,
                         __nv_bfloat16* __restrict__ oH, __nv_bfloat16* __restrict__ oL, int doRelu)
{
    size_t i = ((size_t)blockIdx.x * blockDim.x + threadIdx.x) * 4;
    const float4* a = (const float4*)p;
    float4 v0 = a[i / 4], v1 = a[i / 4 + NH / 4];
    float f[4] = {v0.x + v1.x, v0.y + v1.y, v0.z + v1.z, v0.w + v1.w};
    if (doRelu) {
        #pragma unroll
        for (int j = 0; j < 4; j++) f[j] = fmaxf(f[j], 0.f);
    }
    if (oF) *(float4*)(oF + i) = make_float4(f[0], f[1], f[2], f[3]);
    if (oH) {
        __nv_bfloat16 h[4], l[4];
        #pragma unroll
        for (int j = 0; j < 4; j++) {
            h[j] = __float2bfloat16_rn(f[j]);
            l[j] = __float2bfloat16_rn(f[j] - __bfloat162float(h[j]));
        }
        *(__nv_bfloat162*)(oH + i)     = __nv_bfloat162(h[0], h[1]);
        *(__nv_bfloat162*)(oH + i + 2) = __nv_bfloat162(h[2], h[3]);
        *(__nv_bfloat162*)(oL + i)     = __nv_bfloat162(l[0], l[1]);
        *(__nv_bfloat162*)(oL + i + 2) = __nv_bfloat162(l[2], l[3]);
    }
}

// ---------------- transpose (Wf4 only) ----------------
__global__ void transpose_k(const float* __restrict__ W, float* __restrict__ Wt, int R, int C)
{
    __shared__ float tile[32][33];
    int c0 = blockIdx.x * 32, r0 = blockIdx.y * 32;
    int x = threadIdx.x, y = threadIdx.y;
    #pragma unroll
    for (int dy = 0; dy < 32; dy += 8) {
        int r = r0 + y + dy, c = c0 + x;
        if (r < R && c < C) tile[y + dy][x] = W[(size_t)r * C + c];
    }
    __syncthreads();
    #pragma unroll
    for (int dy = 0; dy < 32; dy += 8) {
        int c = c0 + y + dy, r = r0 + x;
        if (c < C && r < R) Wt[(size_t)c * R + r] = tile[x][y + dy];
    }
}

__global__ void zero_k(float* p, int n)
{
    for (int i = blockIdx.x * blockDim.x + threadIdx.x; i < n; i += gridDim.x * blockDim.x)
        p[i] = 0.f;
}

// ---------------- attention / pooling / softmax ----------------
__global__ void alpha_scatter(const float* __restrict__ q1s, const float* __restrict__ q2,
                              const float* __restrict__ z, const float* __restrict__ Wf3,
                              const int* __restrict__ idx, float* __restrict__ sg)
{
    int n = blockIdx.x, c = threadIdx.x;
    int b = idx[n];
    float q = q1s[b * HID + c] + q2[(size_t)n * HID + c];
    float t = Wf3[c] / (1.f + __expf(-q));
    #pragma unroll
    for (int o = 16; o > 0; o >>= 1) t += __shfl_xor_sync(0xffffffffu, t, o);
    __shared__ float red[8];
    if ((c & 31) == 0) red[c >> 5] = t;
    __syncthreads();
    float alpha = red[0] + red[1] + red[2] + red[3] + red[4] + red[5] + red[6] + red[7];
    atomicAdd(&sg[b * HID + c], alpha * z[(size_t)n * HID + c]);
}

__global__ void sh_kernel(const float* __restrict__ z, const int* __restrict__ last_item,
                          const float* __restrict__ sg, const float* __restrict__ wf4t,
                          const float* __restrict__ bf4,
                          __nv_bfloat16* __restrict__ shh, __nv_bfloat16* __restrict__ shl)
{
    int b = blockIdx.x, c = threadIdx.x;
    __shared__ float srow[2 * HID];
    int li = last_item[b];
    srow[c]       = z[(size_t)li * HID + c];
    srow[HID + c] = sg[b * HID + c];
    __syncthreads();
    float acc = bf4[c];
    #pragma unroll 8
    for (int k = 0; k < 2 * HID; k++) acc += srow[k] * wf4t[k * HID + c];
    __nv_bfloat16 hh = __float2bfloat16_rn(acc);
    shh[b * HID + c] = hh;
    shl[b * HID + c] = __float2bfloat16_rn(acc - __bfloat162float(hh));
}

// reduce LG_GX (max, expsum) partials per session -> gmax/gsum
__global__ void softmax_combine(const float* __restrict__ part,
                                float* __restrict__ gmax, float* __restrict__ gsum)
{
    int b = blockIdx.x, t = threadIdx.x;
    const float* pm = part + (size_t)b * LG_GX;
    const float* ps = part + (size_t)BSESS * LG_GX + (size_t)b * LG_GX;
    float m = -1e30f, s = 0.f;
    for (int i = t; i < LG_GX; i += 256) {
        float m2 = pm[i], s2 = ps[i];
        float M = fmaxf(m, m2);
        s = s * __expf(m - M) + s2 * __expf(m2 - M);
        m = M;
    }
    __shared__ float sm[256], ss[256];
    sm[t] = m; ss[t] = s;
    __syncthreads();
    for (int o = 128; o > 0; o >>= 1) {
        if (t < o) {
            float m2 = sm[t + o], s2 = ss[t + o];
            float M = fmaxf(sm[t], m2);
            ss[t] = ss[t] * __expf(sm[t] - M) + s2 * __expf(m2 - M);
            sm[t] = M;
        }
        __syncthreads();
    }
    if (t == 0) { gmax[b] = sm[0]; gsum[b] = ss[0]; }
}

__global__ void softmax_write(float* __restrict__ out,
                              const float* __restrict__ gmax, const float* __restrict__ gsum)
{
    int b = blockIdx.y;
    int i4 = blockIdx.x * blockDim.x + threadIdx.x;
    if (i4 * 4 >= NITEMS) return;
    float m = gmax[b], inv = 1.f / gsum[b];
    float4* p = (float4*)(out + (size_t)b * NITEMS) + i4;
    float4 v = *p;
    v.x = __expf(v.x - m) * inv; v.y = __expf(v.y - m) * inv;
    v.z = __expf(v.z - m) * inv; v.w = __expf(v.w - m) * inv;
    *p = v;
}

// ---------------- launcher ----------------
extern "C" void kernel_launch(void* const* d_in, const int* in_sizes, int n_in,
                              void* d_out, int out_size)
{
    const float* adj       = (const float*)d_in[0];
    const int*   items     = (const int*)  d_in[1];
    const int*   last_item = (const int*)  d_in[2];
    const int*   idx       = (const int*)  d_in[3];
    const float* emb       = (const float*)d_in[4];
    const float* W1  = (const float*)d_in[5];
    const float* b1  = (const float*)d_in[6];
    const float* W2  = (const float*)d_in[7];
    const float* b2  = (const float*)d_in[8];
    const float* Wf1 = (const float*)d_in[9];
    const float* bf1 = (const float*)d_in[10];
    const float* Wf2 = (const float*)d_in[11];
    const float* bf2 = (const float*)d_in[12];
    const float* Wf3 = (const float*)d_in[13];
    const float* Wf4 = (const float*)d_in[14];
    const float* bf4 = (const float*)d_in[15];
    float* out = (float*)d_out;

    float* fb = nullptr;
    cudaGetSymbolAddress((void**)&fb, g_f);
    float* z    = fb + F_Z;
    float* q2   = fb + F_Q2;
    float* part = fb + F_P;
    float* q1s  = fb + F_Q1S;
    float* sg   = fb + F_SG;
    float* wf4t = fb + F_WF4T;
    float* gmax = fb + F_MAX;
    float* gsum = fb + F_SUM;

    __nv_bfloat16 *adjh, *adjl, *embh, *embl, *xh, *xl, *hh, *hl, *zh, *zl, *shh, *shl;
    __nv_bfloat16 *w1h, *w1l, *w2h, *w2l, *wf1h, *wf1l, *wf2h, *wf2l;
    cudaGetSymbolAddress((void**)&adjh, g_adj_h);
    cudaGetSymbolAddress((void**)&adjl, g_adj_l);
    cudaGetSymbolAddress((void**)&embh, g_emb_h);
    cudaGetSymbolAddress((void**)&embl, g_emb_l);
    cudaGetSymbolAddress((void**)&xh,   g_x_h);
    cudaGetSymbolAddress((void**)&xl,   g_x_l);
    cudaGetSymbolAddress((void**)&hh,   g_h_h);
    cudaGetSymbolAddress((void**)&hl,   g_h_l);
    cudaGetSymbolAddress((void**)&zh,   g_z_h);
    cudaGetSymbolAddress((void**)&zl,   g_z_l);
    cudaGetSymbolAddress((void**)&shh,  g_sh_h);
    cudaGetSymbolAddress((void**)&shl,  g_sh_l);
    cudaGetSymbolAddress((void**)&w1h,  g_w1h);  cudaGetSymbolAddress((void**)&w1l,  g_w1l);
    cudaGetSymbolAddress((void**)&w2h,  g_w2h);  cudaGetSymbolAddress((void**)&w2l,  g_w2l);
    cudaGetSymbolAddress((void**)&wf1h, g_wf1h); cudaGetSymbolAddress((void**)&wf1l, g_wf1l);
    cudaGetSymbolAddress((void**)&wf2h, g_wf2h); cudaGetSymbolAddress((void**)&wf2l, g_wf2l);

    static bool inited = false;
    if (!inited) {
        cudaFuncSetAttribute(gemm_sp, cudaFuncAttributeMaxDynamicSharedMemorySize, SP_SMEM);
        inited = true;
    }

    // weight splits + Wf4 transpose + zero
    cvt_split<<<16, 256>>>(W1,  w1h,  w1l,  65536, 65536);
    cvt_split<<<16, 256>>>(W2,  w2h,  w2l,  65536, 65536);
    cvt_split<<<16, 256>>>(Wf1, wf1h, wf1l, 65536, 65536);
    cvt_split<<<16, 256>>>(Wf2, wf2h, wf2l, 65536, 65536);
    transpose_k<<<dim3(16, 8), dim3(32, 8)>>>(Wf4, wf4t, HID, 2 * HID);
    zero_k<<<256, 256>>>(sg, BSESS * HID);
    cvt_split<<<2048, 256>>>(adj, adjh, adjl, (size_t)NNODES * NNODES, (size_t)NNODES * NNODES);
    cvt_split<<<1024, 256>>>(emb, embh, embl, (size_t)NITEMS * HID, (size_t)NITEMS_PAD * HID);

    // t1^T[hid][node] = W1 @ emb[items]^T + b1  (split output xh/xl)
    gemm_sp<<<dim3(64, 2, 1), 256, SP_SMEM>>>(w1h, w1l, HID, nullptr,
                                              embh, embl, HID, items,
                                              nullptr, xh, xl, NNODES, 0,
                                              b1, nullptr, nullptr, NNODES, HID);
    // h = relu(adj @ t1): split-K x2 -> split bf16 hh/hl
    gemm_sp<<<dim3(2, 64, 2), 256, SP_SMEM>>>(adjh, adjl, NNODES, nullptr,
                                              xh, xl, NNODES, nullptr,
                                              part, nullptr, nullptr, HID, NH,
                                              nullptr, nullptr, nullptr, HID, NNODES / 2);
    combine2<<<NH / 1024, 256>>>(part, nullptr, hh, hl, 1);
    // t2^T = W2 @ h^T + b2
    gemm_sp<<<dim3(64, 2, 1), 256, SP_SMEM>>>(w2h, w2l, HID, nullptr,
                                              hh, hl, HID, nullptr,
                                              nullptr, xh, xl, NNODES, 0,
                                              b2, nullptr, nullptr, NNODES, HID);
    // z = adj @ t2 -> z fp32 + zh/zl
    gemm_sp<<<dim3(2, 64, 2), 256, SP_SMEM>>>(adjh, adjl, NNODES, nullptr,
                                              xh, xl, NNODES, nullptr,
                                              part, nullptr, nullptr, HID, NH,
                                              nullptr, nullptr, nullptr, HID, NNODES / 2);
    combine2<<<NH / 1024, 256>>>(part, z, zh, zl, 0);
    // q1s = z[last_item] @ Wf1^T + bf1
    gemm_sp<<<dim3(2, 4, 1), 256, SP_SMEM>>>(zh, zl, HID, last_item,
                                             wf1h, wf1l, HID, nullptr,
                                             q1s, nullptr, nullptr, HID, 0,
                                             nullptr, bf1, nullptr, HID, HID);
    // q2 = z @ Wf2^T + bf2
    gemm_sp<<<dim3(2, 64, 1), 256, SP_SMEM>>>(zh, zl, HID, nullptr,
                                              wf2h, wf2l, HID, nullptr,
                                              q2, nullptr, nullptr, HID, 0,
                                              nullptr, bf2, nullptr, HID, HID);
    alpha_scatter<<<NNODES, 256>>>(q1s, q2, z, Wf3, idx, sg);
    sh_kernel<<<BSESS, 256>>>(z, last_item, sg, wf4t, bf4, shh, shl);
    // logits: out[b][i] = sh[b,:] . emb[i,:]  + fused softmax partials into `part`
    gemm_sp<<<dim3(LG_GX, 4, 1), 256, SP_SMEM>>>(shh, shl, HID, nullptr,
                                                 embh, embl, HID, nullptr,
                                                 out, nullptr, nullptr, NITEMS, 0,
                                                 nullptr, nullptr, part, NITEMS, HID);
    softmax_combine<<<BSESS, 256>>>(part, gmax, gsum);
    softmax_write<<<dim3((NITEMS / 4 + 255) / 256, BSESS), 256>>>(out, gmax, gsum);
}

// round 15
// speedup vs baseline: 1.6742x; 1.0060x over previous
#include <cuda_runtime.h>
#include <cuda_bf16.h>
#include <math.h>
#include <stdint.h>

#define HID 256
#define NNODES 8192
#define BSESS 512
#define NITEMS 100000
#define NITEMS_PAD 100096           // 782 * 128
#define LG_GX 782

// ---------------- static scratch (floats) ----------------
constexpr size_t NH = (size_t)NNODES * HID;
constexpr size_t F_Z    = 0;
constexpr size_t F_Q2   = F_Z   + NH;
constexpr size_t F_P    = F_Q2  + NH;                 // 2 x NH partials (also softmax partials)
constexpr size_t F_Q1S  = F_P   + 2 * NH;
constexpr size_t F_SG   = F_Q1S + (size_t)BSESS * HID;
constexpr size_t F_WF4T = F_SG  + (size_t)BSESS * HID;
constexpr size_t F_MAX  = F_WF4T + (size_t)2 * HID * HID;
constexpr size_t F_SUM  = F_MAX + BSESS;
constexpr size_t F_TOTAL = F_SUM + BSESS;
__device__ float g_f[F_TOTAL];

// bf16 hi/lo split buffers
__device__ __nv_bfloat16 g_adj_h[(size_t)NNODES * NNODES];
__device__ __nv_bfloat16 g_adj_l[(size_t)NNODES * NNODES];
__device__ __nv_bfloat16 g_emb_h[(size_t)NITEMS_PAD * HID];
__device__ __nv_bfloat16 g_emb_l[(size_t)NITEMS_PAD * HID];
__device__ __nv_bfloat16 g_x_h[(size_t)HID * NNODES];
__device__ __nv_bfloat16 g_x_l[(size_t)HID * NNODES];
__device__ __nv_bfloat16 g_h_h[NH], g_h_l[NH];
__device__ __nv_bfloat16 g_z_h[NH], g_z_l[NH];
__device__ __nv_bfloat16 g_sh_h[(size_t)BSESS * HID];
__device__ __nv_bfloat16 g_sh_l[(size_t)BSESS * HID];
__device__ __nv_bfloat16 g_w1h[65536], g_w1l[65536];
__device__ __nv_bfloat16 g_w2h[65536], g_w2l[65536];
__device__ __nv_bfloat16 g_wf1h[65536], g_wf1l[65536];
__device__ __nv_bfloat16 g_wf2h[65536], g_wf2l[65536];

// ---------------- PTX helpers ----------------
__device__ __forceinline__ uint32_t smem_u32(const void* p) {
    uint32_t a;
    asm("{ .reg .u64 t; cvta.to.shared.u64 t, %1; cvt.u32.u64 %0, t; }" : "=r"(a) : "l"(p));
    return a;
}
#define LDM_X4(r, a) \
    asm volatile("ldmatrix.sync.aligned.m8n8.x4.shared.b16 {%0,%1,%2,%3}, [%4];" \
        : "=r"((r)[0]), "=r"((r)[1]), "=r"((r)[2]), "=r"((r)[3]) : "r"(a))
#define MMA16816(c, a, b0, b1) \
    asm volatile("mma.sync.aligned.m16n8k16.row.col.f32.bf16.bf16.f32 " \
        "{%0,%1,%2,%3}, {%4,%5,%6,%7}, {%8,%9}, {%0,%1,%2,%3};" \
        : "+f"((c)[0]), "+f"((c)[1]), "+f"((c)[2]), "+f"((c)[3]) \
        : "r"((a)[0]), "r"((a)[1]), "r"((a)[2]), "r"((a)[3]), "r"(b0), "r"(b1))
#define CP_ASYNC16(dst, src) \
    asm volatile("cp.async.cg.shared.global [%0], [%1], 16;" :: "r"(dst), "l"(src) : "memory")
#define CP_COMMIT() asm volatile("cp.async.commit_group;" ::: "memory")
#define CP_WAIT1()  asm volatile("cp.async.wait_group 1;" ::: "memory")
#define CP_WAIT0()  asm volatile("cp.async.wait_group 0;" ::: "memory")

// ---------------- fp32 -> bf16 hi/lo split (generic) ----------------
__global__ void cvt_split(const float* __restrict__ src, __nv_bfloat16* __restrict__ hi,
                          __nv_bfloat16* __restrict__ lo, size_t nsrc, size_t ntot)
{
    size_t stride = (size_t)gridDim.x * blockDim.x;
    for (size_t t = (size_t)blockIdx.x * blockDim.x + threadIdx.x; t * 4 < ntot; t += stride) {
        size_t i = t * 4;
        float4 v = (i < nsrc) ? *(const float4*)(src + i) : make_float4(0.f, 0.f, 0.f, 0.f);
        float f[4] = {v.x, v.y, v.z, v.w};
        __nv_bfloat16 h[4], l[4];
        #pragma unroll
        for (int j = 0; j < 4; j++) {
            h[j] = __float2bfloat16_rn(f[j]);
            l[j] = __float2bfloat16_rn(f[j] - __bfloat162float(h[j]));
        }
        *(__nv_bfloat162*)(hi + i)     = __nv_bfloat162(h[0], h[1]);
        *(__nv_bfloat162*)(hi + i + 2) = __nv_bfloat162(h[2], h[3]);
        *(__nv_bfloat162*)(lo + i)     = __nv_bfloat162(l[0], l[1]);
        *(__nv_bfloat162*)(lo + i + 2) = __nv_bfloat162(l[2], l[3]);
    }
}

// 4 weight matrices (256x256 each) in one launch; blockIdx.y picks the matrix
__global__ void cvt_split4(const float* __restrict__ W1, const float* __restrict__ W2,
                           const float* __restrict__ Wf1, const float* __restrict__ Wf2,
                           __nv_bfloat16* __restrict__ h1, __nv_bfloat16* __restrict__ l1,
                           __nv_bfloat16* __restrict__ h2, __nv_bfloat16* __restrict__ l2,
                           __nv_bfloat16* __restrict__ h3, __nv_bfloat16* __restrict__ l3,
                           __nv_bfloat16* __restrict__ h4, __nv_bfloat16* __restrict__ l4)
{
    int m = blockIdx.y;
    const float* src = (m == 0) ? W1 : (m == 1) ? W2 : (m == 2) ? Wf1 : Wf2;
    __nv_bfloat16* hi = (m == 0) ? h1 : (m == 1) ? h2 : (m == 2) ? h3 : h4;
    __nv_bfloat16* lo = (m == 0) ? l1 : (m == 1) ? l2 : (m == 2) ? l3 : l4;
    size_t stride = (size_t)gridDim.x * blockDim.x;
    for (size_t t = (size_t)blockIdx.x * blockDim.x + threadIdx.x; t * 4 < 65536; t += stride) {
        size_t i = t * 4;
        float4 v = *(const float4*)(src + i);
        float f[4] = {v.x, v.y, v.z, v.w};
        __nv_bfloat16 h[4], l[4];
        #pragma unroll
        for (int j = 0; j < 4; j++) {
            h[j] = __float2bfloat16_rn(f[j]);
            l[j] = __float2bfloat16_rn(f[j] - __bfloat162float(h[j]));
        }
        *(__nv_bfloat162*)(hi + i)     = __nv_bfloat162(h[0], h[1]);
        *(__nv_bfloat162*)(hi + i + 2) = __nv_bfloat162(h[2], h[3]);
        *(__nv_bfloat162*)(lo + i)     = __nv_bfloat162(l[0], l[1]);
        *(__nv_bfloat162*)(lo + i + 2) = __nv_bfloat162(l[2], l[3]);
    }
}

// ---------------- bf16-split GEMM, BM=128 x BN=128, BK=32, 2 stages, occ 2 ----------------
#define SP_PITCH 80
#define SP_AMAT  10240
#define SP_STAGE 40960
#define SP_SMEM  81920

__global__ __launch_bounds__(256, 2)
void gemm_sp(const __nv_bfloat16* __restrict__ Ah, const __nv_bfloat16* __restrict__ Al,
             int lda, const int* __restrict__ gidxA,
             const __nv_bfloat16* __restrict__ Bh, const __nv_bfloat16* __restrict__ Bl,
             int ldb, const int* __restrict__ gidxB,
             float* __restrict__ C, __nv_bfloat16* __restrict__ hiC, __nv_bfloat16* __restrict__ loC,
             size_t ldc, size_t partStride,
             const float* __restrict__ biasM, const float* __restrict__ biasN,
             float* __restrict__ partials, int Nbound, int K)
{
    extern __shared__ __align__(128) char smem[];
    uint32_t sbase = smem_u32(smem);
    int tid = threadIdx.x, wid = tid >> 5, lane = tid & 31;
    int n0 = blockIdx.x * 128;
    int m0 = blockIdx.y * 128;
    int kbase = blockIdx.z * K;
    int wm = (wid >> 2) * 64;
    int wn = (wid & 3) * 32;

    float acc[4][4][4];
    #pragma unroll
    for (int a = 0; a < 4; a++)
        #pragma unroll
        for (int b = 0; b < 4; b++)
            #pragma unroll
            for (int cc = 0; cc < 4; cc++) acc[a][b][cc] = 0.f;

    auto copy_stage = [&](int s, int k0e) {
        uint32_t dst0 = sbase + (uint32_t)s * SP_STAGE;
        int colb = kbase + k0e + (tid & 3) * 8;
        #pragma unroll
        for (int j = 0; j < 8; j++) {
            int c = j * 256 + tid;
            int mat = c >> 9;
            int row = (c >> 2) & 127;
            const __nv_bfloat16* g;
            if (mat < 2) {
                int r = m0 + row;
                if (gidxA) r = gidxA[r];
                g = (mat ? Al : Ah) + (size_t)r * lda + colb;
            } else {
                int r = n0 + row;
                if (gidxB) r = gidxB[r];
                g = ((mat == 3) ? Bl : Bh) + (size_t)r * ldb + colb;
            }
            uint32_t dst = dst0 + (uint32_t)mat * SP_AMAT + (uint32_t)row * SP_PITCH
                         + (uint32_t)(tid & 3) * 16;
            CP_ASYNC16(dst, g);
        }
    };

    int kt = K / 32;
    copy_stage(0, 0);
    CP_COMMIT();

    for (int ki = 0; ki < kt; ki++) {
        int s = ki & 1;
        if (ki + 1 < kt) {
            copy_stage(s ^ 1, (ki + 1) * 32);
            CP_COMMIT();
            CP_WAIT1();
        } else {
            CP_WAIT0();
        }
        __syncthreads();

        uint32_t As  = sbase + (uint32_t)s * SP_STAGE;
        uint32_t Asl = As + SP_AMAT;
        uint32_t Bs  = As + 2 * SP_AMAT;
        uint32_t Bsl = As + 3 * SP_AMAT;

        #pragma unroll
        for (int kb = 0; kb < 32; kb += 16) {
            uint32_t af[4][4], b1[2][4], b2[2][4];
            uint32_t aoff = (uint32_t)(wm + (lane & 15)) * SP_PITCH
                          + (uint32_t)(kb + ((lane >> 4) << 3)) * 2;
            uint32_t boff = (uint32_t)(wn + (lane & 7) + ((lane >> 1) & 8)) * SP_PITCH
                          + (uint32_t)(kb + ((lane >> 3) & 1) * 8) * 2;
            #pragma unroll
            for (int mt = 0; mt < 4; mt++) LDM_X4(af[mt], As + aoff + mt * 16 * SP_PITCH);
            #pragma unroll
            for (int p = 0; p < 2; p++)    LDM_X4(b1[p], Bs + boff + p * 16 * SP_PITCH);
            #pragma unroll
            for (int mt = 0; mt < 4; mt++)
                #pragma unroll
                for (int nt = 0; nt < 4; nt++) {
                    int p = nt >> 1, q = (nt & 1) * 2;
                    MMA16816(acc[mt][nt], af[mt], b1[p][q], b1[p][q + 1]);
                }
            #pragma unroll
            for (int p = 0; p < 2; p++)    LDM_X4(b2[p], Bsl + boff + p * 16 * SP_PITCH);
            #pragma unroll
            for (int mt = 0; mt < 4; mt++)
                #pragma unroll
                for (int nt = 0; nt < 4; nt++) {
                    int p = nt >> 1, q = (nt & 1) * 2;
                    MMA16816(acc[mt][nt], af[mt], b2[p][q], b2[p][q + 1]);
                }
            #pragma unroll
            for (int mt = 0; mt < 4; mt++) LDM_X4(af[mt], Asl + aoff + mt * 16 * SP_PITCH);
            #pragma unroll
            for (int mt = 0; mt < 4; mt++)
                #pragma unroll
                for (int nt = 0; nt < 4; nt++) {
                    int p = nt >> 1, q = (nt & 1) * 2;
                    MMA16816(acc[mt][nt], af[mt], b1[p][q], b1[p][q + 1]);
                }
        }
        __syncthreads();
    }

    // -------- epilogue: stores --------
    #pragma unroll
    for (int mt = 0; mt < 4; mt++)
        #pragma unroll
        for (int nt = 0; nt < 4; nt++) {
            int m = m0 + wm + mt * 16 + (lane >> 2);
            int n = n0 + wn + nt * 8 + (lane & 3) * 2;
            if (n >= Nbound) continue;
            float bm0 = biasM ? biasM[m] : 0.f;
            float bm1 = biasM ? biasM[m + 8] : 0.f;
            float bn0 = biasN ? biasN[n] : 0.f;
            float bn1 = biasN ? biasN[n + 1] : 0.f;
            float v0 = acc[mt][nt][0] + bm0 + bn0;
            float v1 = acc[mt][nt][1] + bm0 + bn1;
            float v2 = acc[mt][nt][2] + bm1 + bn0;
            float v3 = acc[mt][nt][3] + bm1 + bn1;
            if (hiC) {
                __nv_bfloat16 h0 = __float2bfloat16_rn(v0), h1 = __float2bfloat16_rn(v1);
                __nv_bfloat16 h2 = __float2bfloat16_rn(v2), h3 = __float2bfloat16_rn(v3);
                size_t o0 = (size_t)m * ldc + n, o1 = (size_t)(m + 8) * ldc + n;
                *(__nv_bfloat162*)(hiC + o0) = __nv_bfloat162(h0, h1);
                *(__nv_bfloat162*)(hiC + o1) = __nv_bfloat162(h2, h3);
                *(__nv_bfloat162*)(loC + o0) = __nv_bfloat162(
                    __float2bfloat16_rn(v0 - __bfloat162float(h0)),
                    __float2bfloat16_rn(v1 - __bfloat162float(h1)));
                *(__nv_bfloat162*)(loC + o1) = __nv_bfloat162(
                    __float2bfloat16_rn(v2 - __bfloat162float(h2)),
                    __float2bfloat16_rn(v3 - __bfloat162float(h3)));
            } else {
                float* Cp = C + (size_t)blockIdx.z * partStride;
                *(float2*)&Cp[(size_t)m * ldc + n]       = make_float2(v0, v1);
                *(float2*)&Cp[(size_t)(m + 8) * ldc + n] = make_float2(v2, v3);
            }
        }

    // -------- epilogue: fused softmax partials (shuffle-based) --------
    if (partials) {
        float* sred = (float*)smem;              // [128][4] per-warp-band max
        float* ssum = (float*)(smem + 2048);     // [128][4] per-warp-band expsum
        #pragma unroll
        for (int mt = 0; mt < 4; mt++)
            #pragma unroll
            for (int half = 0; half < 2; half++) {
                float vm = -1e30f;
                #pragma unroll
                for (int nt = 0; nt < 4; nt++) {
                    int n = n0 + wn + nt * 8 + (lane & 3) * 2;
                    if (n < Nbound)     vm = fmaxf(vm, acc[mt][nt][half * 2]);
                    if (n + 1 < Nbound) vm = fmaxf(vm, acc[mt][nt][half * 2 + 1]);
                }
                vm = fmaxf(vm, __shfl_xor_sync(0xffffffffu, vm, 1));
                vm = fmaxf(vm, __shfl_xor_sync(0xffffffffu, vm, 2));
                int rl = wm + mt * 16 + (lane >> 2) + half * 8;
                if ((lane & 3) == 0) sred[rl * 4 + (wid & 3)] = vm;
            }
        __syncthreads();
        #pragma unroll
        for (int mt = 0; mt < 4; mt++)
            #pragma unroll
            for (int half = 0; half < 2; half++) {
                int rl = wm + mt * 16 + (lane >> 2) + half * 8;
                float rm = fmaxf(fmaxf(sred[rl * 4 + 0], sred[rl * 4 + 1]),
                                 fmaxf(sred[rl * 4 + 2], sred[rl * 4 + 3]));
                float s = 0.f;
                #pragma unroll
                for (int nt = 0; nt < 4; nt++) {
                    int n = n0 + wn + nt * 8 + (lane & 3) * 2;
                    if (n < Nbound)     s += __expf(acc[mt][nt][half * 2] - rm);
                    if (n + 1 < Nbound) s += __expf(acc[mt][nt][half * 2 + 1] - rm);
                }
                s += __shfl_xor_sync(0xffffffffu, s, 1);
                s += __shfl_xor_sync(0xffffffffu, s, 2);
                if ((lane & 3) == 0) ssum[rl * 4 + (wid & 3)] = s;
            }
        __syncthreads();
        if (tid < 128) {
            float rm = fmaxf(fmaxf(sred[tid * 4 + 0], sred[tid * 4 + 1]),
                             fmaxf(sred[tid * 4 + 2], sred[tid * 4 + 3]));
            float rs = ssum[tid * 4 + 0] + ssum[tid * 4 + 1]
                     + ssum[tid * 4 + 2] + ssum[tid * 4 + 3];
            size_t gx = gridDim.x;
            size_t rows = (size_t)gridDim.y * 128;
            partials[(size_t)(m0 + tid) * gx + blockIdx.x] = rm;
            partials[rows * gx + (size_t)(m0 + tid) * gx + blockIdx.x] = rs;
        }
    }
}

// combine split-K partials: fp32 and/or split bf16 output
__global__ void combine2(const float* __restrict__ p, float* __restrict__ oF,
                         __nv_bfloat16* __restrict__ oH, __nv_bfloat16* __restrict__ oL, int doRelu)
{
    size_t i = ((size_t)blockIdx.x * blockDim.x + threadIdx.x) * 4;
    const float4* a = (const float4*)p;
    float4 v0 = a[i / 4], v1 = a[i / 4 + NH / 4];
    float f[4] = {v0.x + v1.x, v0.y + v1.y, v0.z + v1.z, v0.w + v1.w};
    if (doRelu) {
        #pragma unroll
        for (int j = 0; j < 4; j++) f[j] = fmaxf(f[j], 0.f);
    }
    if (oF) *(float4*)(oF + i) = make_float4(f[0], f[1], f[2], f[3]);
    if (oH) {
        __nv_bfloat16 h[4], l[4];
        #pragma unroll
        for (int j = 0; j < 4; j++) {
            h[j] = __float2bfloat16_rn(f[j]);
            l[j] = __float2bfloat16_rn(f[j] - __bfloat162float(h[j]));
        }
        *(__nv_bfloat162*)(oH + i)     = __nv_bfloat162(h[0], h[1]);
        *(__nv_bfloat162*)(oH + i + 2) = __nv_bfloat162(h[2], h[3]);
        *(__nv_bfloat162*)(oL + i)     = __nv_bfloat162(l[0], l[1]);
        *(__nv_bfloat162*)(oL + i + 2) = __nv_bfloat162(l[2], l[3]);
    }
}

// ---------------- transpose (Wf4 only) ----------------
__global__ void transpose_k(const float* __restrict__ W, float* __restrict__ Wt, int R, int C)
{
    __shared__ float tile[32][33];
    int c0 = blockIdx.x * 32, r0 = blockIdx.y * 32;
    int x = threadIdx.x, y = threadIdx.y;
    #pragma unroll
    for (int dy = 0; dy < 32; dy += 8) {
        int r = r0 + y + dy, c = c0 + x;
        if (r < R && c < C) tile[y + dy][x] = W[(size_t)r * C + c];
    }
    __syncthreads();
    #pragma unroll
    for (int dy = 0; dy < 32; dy += 8) {
        int c = c0 + y + dy, r = r0 + x;
        if (c < C && r < R) Wt[(size_t)c * R + r] = tile[x][y + dy];
    }
}

// ---------------- attention / pooling / softmax ----------------
__global__ void alpha_scatter(const float* __restrict__ q1s, const float* __restrict__ q2,
                              const float* __restrict__ z, const float* __restrict__ Wf3,
                              const int* __restrict__ idx, float* __restrict__ sg)
{
    int n = blockIdx.x, c = threadIdx.x;
    int b = idx[n];
    float q = q1s[b * HID + c] + q2[(size_t)n * HID + c];
    float t = Wf3[c] / (1.f + __expf(-q));
    #pragma unroll
    for (int o = 16; o > 0; o >>= 1) t += __shfl_xor_sync(0xffffffffu, t, o);
    __shared__ float red[8];
    if ((c & 31) == 0) red[c >> 5] = t;
    __syncthreads();
    float alpha = red[0] + red[1] + red[2] + red[3] + red[4] + red[5] + red[6] + red[7];
    atomicAdd(&sg[b * HID + c], alpha * z[(size_t)n * HID + c]);
}

__global__ void sh_kernel(const float* __restrict__ z, const int* __restrict__ last_item,
                          const float* __restrict__ sg, const float* __restrict__ wf4t,
                          const float* __restrict__ bf4,
                          __nv_bfloat16* __restrict__ shh, __nv_bfloat16* __restrict__ shl)
{
    int b = blockIdx.x, c = threadIdx.x;
    __shared__ float srow[2 * HID];
    int li = last_item[b];
    srow[c]       = z[(size_t)li * HID + c];
    srow[HID + c] = sg[b * HID + c];
    __syncthreads();
    float acc = bf4[c];
    #pragma unroll 8
    for (int k = 0; k < 2 * HID; k++) acc += srow[k] * wf4t[k * HID + c];
    __nv_bfloat16 hh = __float2bfloat16_rn(acc);
    shh[b * HID + c] = hh;
    shl[b * HID + c] = __float2bfloat16_rn(acc - __bfloat162float(hh));
}

// reduce LG_GX (max, expsum) partials per session -> gmax/gsum
__global__ void softmax_combine(const float* __restrict__ part,
                                float* __restrict__ gmax, float* __restrict__ gsum)
{
    int b = blockIdx.x, t = threadIdx.x;
    const float* pm = part + (size_t)b * LG_GX;
    const float* ps = part + (size_t)BSESS * LG_GX + (size_t)b * LG_GX;
    float m = -1e30f, s = 0.f;
    for (int i = t; i < LG_GX; i += 256) {
        float m2 = pm[i], s2 = ps[i];
        float M = fmaxf(m, m2);
        s = s * __expf(m - M) + s2 * __expf(m2 - M);
        m = M;
    }
    __shared__ float sm[256], ss[256];
    sm[t] = m; ss[t] = s;
    __syncthreads();
    for (int o = 128; o > 0; o >>= 1) {
        if (t < o) {
            float m2 = sm[t + o], s2 = ss[t + o];
            float M = fmaxf(sm[t], m2);
            ss[t] = ss[t] * __expf(sm[t] - M) + s2 * __expf(m2 - M);
            sm[t] = M;
        }
        __syncthreads();
    }
    if (t == 0) { gmax[b] = sm[0]; gsum[b] = ss[0]; }
}

__global__ void softmax_write(float* __restrict__ out,
                              const float* __restrict__ gmax, const float* __restrict__ gsum)
{
    int b = blockIdx.y;
    int i4 = blockIdx.x * blockDim.x + threadIdx.x;
    if (i4 * 4 >= NITEMS) return;
    float m = gmax[b], inv = 1.f / gsum[b];
    float4* p = (float4*)(out + (size_t)b * NITEMS) + i4;
    float4 v = *p;
    v.x = __expf(v.x - m) * inv; v.y = __expf(v.y - m) * inv;
    v.z = __expf(v.z - m) * inv; v.w = __expf(v.w - m) * inv;
    *p = v;
}

// ---------------- launcher ----------------
extern "C" void kernel_launch(void* const* d_in, const int* in_sizes, int n_in,
                              void* d_out, int out_size)
{
    const float* adj       = (const float*)d_in[0];
    const int*   items     = (const int*)  d_in[1];
    const int*   last_item = (const int*)  d_in[2];
    const int*   idx       = (const int*)  d_in[3];
    const float* emb       = (const float*)d_in[4];
    const float* W1  = (const float*)d_in[5];
    const float* b1  = (const float*)d_in[6];
    const float* W2  = (const float*)d_in[7];
    const float* b2  = (const float*)d_in[8];
    const float* Wf1 = (const float*)d_in[9];
    const float* bf1 = (const float*)d_in[10];
    const float* Wf2 = (const float*)d_in[11];
    const float* bf2 = (const float*)d_in[12];
    const float* Wf3 = (const float*)d_in[13];
    const float* Wf4 = (const float*)d_in[14];
    const float* bf4 = (const float*)d_in[15];
    float* out = (float*)d_out;

    float* fb = nullptr;
    cudaGetSymbolAddress((void**)&fb, g_f);
    float* z    = fb + F_Z;
    float* q2   = fb + F_Q2;
    float* part = fb + F_P;
    float* q1s  = fb + F_Q1S;
    float* sg   = fb + F_SG;
    float* wf4t = fb + F_WF4T;
    float* gmax = fb + F_MAX;
    float* gsum = fb + F_SUM;

    __nv_bfloat16 *adjh, *adjl, *embh, *embl, *xh, *xl, *hh, *hl, *zh, *zl, *shh, *shl;
    __nv_bfloat16 *w1h, *w1l, *w2h, *w2l, *wf1h, *wf1l, *wf2h, *wf2l;
    cudaGetSymbolAddress((void**)&adjh, g_adj_h);
    cudaGetSymbolAddress((void**)&adjl, g_adj_l);
    cudaGetSymbolAddress((void**)&embh, g_emb_h);
    cudaGetSymbolAddress((void**)&embl, g_emb_l);
    cudaGetSymbolAddress((void**)&xh,   g_x_h);
    cudaGetSymbolAddress((void**)&xl,   g_x_l);
    cudaGetSymbolAddress((void**)&hh,   g_h_h);
    cudaGetSymbolAddress((void**)&hl,   g_h_l);
    cudaGetSymbolAddress((void**)&zh,   g_z_h);
    cudaGetSymbolAddress((void**)&zl,   g_z_l);
    cudaGetSymbolAddress((void**)&shh,  g_sh_h);
    cudaGetSymbolAddress((void**)&shl,  g_sh_l);
    cudaGetSymbolAddress((void**)&w1h,  g_w1h);  cudaGetSymbolAddress((void**)&w1l,  g_w1l);
    cudaGetSymbolAddress((void**)&w2h,  g_w2h);  cudaGetSymbolAddress((void**)&w2l,  g_w2l);
    cudaGetSymbolAddress((void**)&wf1h, g_wf1h); cudaGetSymbolAddress((void**)&wf1l, g_wf1l);
    cudaGetSymbolAddress((void**)&wf2h, g_wf2h); cudaGetSymbolAddress((void**)&wf2l, g_wf2l);

    static bool inited = false;
    if (!inited) {
        cudaFuncSetAttribute(gemm_sp, cudaFuncAttributeMaxDynamicSharedMemorySize, SP_SMEM);
        inited = true;
    }

    // prep: weight splits (one launch), Wf4 transpose, sg zero (memset node), big splits
    cvt_split4<<<dim3(16, 4), 256>>>(W1, W2, Wf1, Wf2,
                                     w1h, w1l, w2h, w2l, wf1h, wf1l, wf2h, wf2l);
    transpose_k<<<dim3(16, 8), dim3(32, 8)>>>(Wf4, wf4t, HID, 2 * HID);
    cudaMemsetAsync(sg, 0, (size_t)BSESS * HID * sizeof(float));
    cvt_split<<<2048, 256>>>(adj, adjh, adjl, (size_t)NNODES * NNODES, (size_t)NNODES * NNODES);
    cvt_split<<<1024, 256>>>(emb, embh, embl, (size_t)NITEMS * HID, (size_t)NITEMS_PAD * HID);

    // t1^T[hid][node] = W1 @ emb[items]^T + b1  (split output xh/xl)
    gemm_sp<<<dim3(64, 2, 1), 256, SP_SMEM>>>(w1h, w1l, HID, nullptr,
                                              embh, embl, HID, items,
                                              nullptr, xh, xl, NNODES, 0,
                                              b1, nullptr, nullptr, NNODES, HID);
    // h = relu(adj @ t1): split-K x2 -> split bf16 hh/hl
    gemm_sp<<<dim3(2, 64, 2), 256, SP_SMEM>>>(adjh, adjl, NNODES, nullptr,
                                              xh, xl, NNODES, nullptr,
                                              part, nullptr, nullptr, HID, NH,
                                              nullptr, nullptr, nullptr, HID, NNODES / 2);
    combine2<<<NH / 1024, 256>>>(part, nullptr, hh, hl, 1);
    // t2^T = W2 @ h^T + b2
    gemm_sp<<<dim3(64, 2, 1), 256, SP_SMEM>>>(w2h, w2l, HID, nullptr,
                                              hh, hl, HID, nullptr,
                                              nullptr, xh, xl, NNODES, 0,
                                              b2, nullptr, nullptr, NNODES, HID);
    // z = adj @ t2 -> z fp32 + zh/zl
    gemm_sp<<<dim3(2, 64, 2), 256, SP_SMEM>>>(adjh, adjl, NNODES, nullptr,
                                              xh, xl, NNODES, nullptr,
                                              part, nullptr, nullptr, HID, NH,
                                              nullptr, nullptr, nullptr, HID, NNODES / 2);
    combine2<<<NH / 1024, 256>>>(part, z, zh, zl, 0);
    // q1s = z[last_item] @ Wf1^T + bf1
    gemm_sp<<<dim3(2, 4, 1), 256, SP_SMEM>>>(zh, zl, HID, last_item,
                                             wf1h, wf1l, HID, nullptr,
                                             q1s, nullptr, nullptr, HID, 0,
                                             nullptr, bf1, nullptr, HID, HID);
    // q2 = z @ Wf2^T + bf2
    gemm_sp<<<dim3(2, 64, 1), 256, SP_SMEM>>>(zh, zl, HID, nullptr,
                                              wf2h, wf2l, HID, nullptr,
                                              q2, nullptr, nullptr, HID, 0,
                                              nullptr, bf2, nullptr, HID, HID);
    alpha_scatter<<<NNODES, 256>>>(q1s, q2, z, Wf3, idx, sg);
    sh_kernel<<<BSESS, 256>>>(z, last_item, sg, wf4t, bf4, shh, shl);
    // logits: out[b][i] = sh[b,:] . emb[i,:]  + fused softmax partials (shuffle-reduced)
    gemm_sp<<<dim3(LG_GX, 4, 1), 256, SP_SMEM>>>(shh, shl, HID, nullptr,
                                                 embh, embl, HID, nullptr,
                                                 out, nullptr, nullptr, NITEMS, 0,
                                                 nullptr, nullptr, part, NITEMS, HID);
    softmax_combine<<<BSESS, 256>>>(part, gmax, gsum);
    softmax_write<<<dim3((NITEMS / 4 + 255) / 256, BSESS), 256>>>(out, gmax, gsum);
}

// round 16
// speedup vs baseline: 1.6814x; 1.0043x over previous
#include <cuda_runtime.h>
#include <cuda_bf16.h>
#include <math.h>
#include <stdint.h>

#define HID 256
#define NNODES 8192
#define BSESS 512
#define NITEMS 100000
#define NITEMS_PAD 100096           // 782 * 128
#define LG_GX 782

// ---------------- static scratch (floats) ----------------
constexpr size_t NH = (size_t)NNODES * HID;
constexpr size_t F_Z    = 0;
constexpr size_t F_Q2   = F_Z   + NH;
constexpr size_t F_P    = F_Q2  + NH;                 // 2 x NH partials (also softmax partials)
constexpr size_t F_Q1S  = F_P   + 2 * NH;
constexpr size_t F_SG   = F_Q1S + (size_t)BSESS * HID;
constexpr size_t F_WF4T = F_SG  + (size_t)BSESS * HID;
constexpr size_t F_MAX  = F_WF4T + (size_t)2 * HID * HID;
constexpr size_t F_SUM  = F_MAX + BSESS;
constexpr size_t F_TOTAL = F_SUM + BSESS;
__device__ float g_f[F_TOTAL];

// bf16 hi/lo split buffers
__device__ __nv_bfloat16 g_adj_h[(size_t)NNODES * NNODES];
__device__ __nv_bfloat16 g_adj_l[(size_t)NNODES * NNODES];
__device__ __nv_bfloat16 g_emb_h[(size_t)NITEMS_PAD * HID];
__device__ __nv_bfloat16 g_emb_l[(size_t)NITEMS_PAD * HID];
__device__ __nv_bfloat16 g_x_h[(size_t)HID * NNODES];
__device__ __nv_bfloat16 g_x_l[(size_t)HID * NNODES];
__device__ __nv_bfloat16 g_h_h[NH], g_h_l[NH];
__device__ __nv_bfloat16 g_z_h[NH], g_z_l[NH];
__device__ __nv_bfloat16 g_sh_h[(size_t)BSESS * HID];
__device__ __nv_bfloat16 g_sh_l[(size_t)BSESS * HID];
__device__ __nv_bfloat16 g_w1h[65536], g_w1l[65536];
__device__ __nv_bfloat16 g_w2h[65536], g_w2l[65536];
__device__ __nv_bfloat16 g_wf1h[65536], g_wf1l[65536];
__device__ __nv_bfloat16 g_wf2h[65536], g_wf2l[65536];

// ---------------- PTX helpers ----------------
__device__ __forceinline__ uint32_t smem_u32(const void* p) {
    uint32_t a;
    asm("{ .reg .u64 t; cvta.to.shared.u64 t, %1; cvt.u32.u64 %0, t; }" : "=r"(a) : "l"(p));
    return a;
}
#define LDM_X4(r, a) \
    asm volatile("ldmatrix.sync.aligned.m8n8.x4.shared.b16 {%0,%1,%2,%3}, [%4];" \
        : "=r"((r)[0]), "=r"((r)[1]), "=r"((r)[2]), "=r"((r)[3]) : "r"(a))
#define MMA16816(c, a, b0, b1) \
    asm volatile("mma.sync.aligned.m16n8k16.row.col.f32.bf16.bf16.f32 " \
        "{%0,%1,%2,%3}, {%4,%5,%6,%7}, {%8,%9}, {%0,%1,%2,%3};" \
        : "+f"((c)[0]), "+f"((c)[1]), "+f"((c)[2]), "+f"((c)[3]) \
        : "r"((a)[0]), "r"((a)[1]), "r"((a)[2]), "r"((a)[3]), "r"(b0), "r"(b1))
#define CP_ASYNC16(dst, src) \
    asm volatile("cp.async.cg.shared.global [%0], [%1], 16;" :: "r"(dst), "l"(src) : "memory")
#define CP_COMMIT() asm volatile("cp.async.commit_group;" ::: "memory")
#define CP_WAIT1()  asm volatile("cp.async.wait_group 1;" ::: "memory")
#define CP_WAIT0()  asm volatile("cp.async.wait_group 0;" ::: "memory")

// ---------------- fp32 -> bf16 hi/lo split (generic) ----------------
__global__ void cvt_split(const float* __restrict__ src, __nv_bfloat16* __restrict__ hi,
                          __nv_bfloat16* __restrict__ lo, size_t nsrc, size_t ntot)
{
    size_t stride = (size_t)gridDim.x * blockDim.x;
    for (size_t t = (size_t)blockIdx.x * blockDim.x + threadIdx.x; t * 4 < ntot; t += stride) {
        size_t i = t * 4;
        float4 v = (i < nsrc) ? *(const float4*)(src + i) : make_float4(0.f, 0.f, 0.f, 0.f);
        float f[4] = {v.x, v.y, v.z, v.w};
        __nv_bfloat16 h[4], l[4];
        #pragma unroll
        for (int j = 0; j < 4; j++) {
            h[j] = __float2bfloat16_rn(f[j]);
            l[j] = __float2bfloat16_rn(f[j] - __bfloat162float(h[j]));
        }
        *(__nv_bfloat162*)(hi + i)     = __nv_bfloat162(h[0], h[1]);
        *(__nv_bfloat162*)(hi + i + 2) = __nv_bfloat162(h[2], h[3]);
        *(__nv_bfloat162*)(lo + i)     = __nv_bfloat162(l[0], l[1]);
        *(__nv_bfloat162*)(lo + i + 2) = __nv_bfloat162(l[2], l[3]);
    }
}

// 4 weight matrices (256x256 each) in one launch; blockIdx.y picks the matrix
__global__ void cvt_split4(const float* __restrict__ W1, const float* __restrict__ W2,
                           const float* __restrict__ Wf1, const float* __restrict__ Wf2,
                           __nv_bfloat16* __restrict__ h1, __nv_bfloat16* __restrict__ l1,
                           __nv_bfloat16* __restrict__ h2, __nv_bfloat16* __restrict__ l2,
                           __nv_bfloat16* __restrict__ h3, __nv_bfloat16* __restrict__ l3,
                           __nv_bfloat16* __restrict__ h4, __nv_bfloat16* __restrict__ l4)
{
    int m = blockIdx.y;
    const float* src = (m == 0) ? W1 : (m == 1) ? W2 : (m == 2) ? Wf1 : Wf2;
    __nv_bfloat16* hi = (m == 0) ? h1 : (m == 1) ? h2 : (m == 2) ? h3 : h4;
    __nv_bfloat16* lo = (m == 0) ? l1 : (m == 1) ? l2 : (m == 2) ? l3 : l4;
    size_t stride = (size_t)gridDim.x * blockDim.x;
    for (size_t t = (size_t)blockIdx.x * blockDim.x + threadIdx.x; t * 4 < 65536; t += stride) {
        size_t i = t * 4;
        float4 v = *(const float4*)(src + i);
        float f[4] = {v.x, v.y, v.z, v.w};
        __nv_bfloat16 h[4], l[4];
        #pragma unroll
        for (int j = 0; j < 4; j++) {
            h[j] = __float2bfloat16_rn(f[j]);
            l[j] = __float2bfloat16_rn(f[j] - __bfloat162float(h[j]));
        }
        *(__nv_bfloat162*)(hi + i)     = __nv_bfloat162(h[0], h[1]);
        *(__nv_bfloat162*)(hi + i + 2) = __nv_bfloat162(h[2], h[3]);
        *(__nv_bfloat162*)(lo + i)     = __nv_bfloat162(l[0], l[1]);
        *(__nv_bfloat162*)(lo + i + 2) = __nv_bfloat162(l[2], l[3]);
    }
}

// ---------------- bf16-split GEMM, BM=128 x BN=128, BK=32, 2 stages, occ 2 ----------------
// swapXY: m0 from blockIdx.x, n0 from blockIdx.y (for B-tile L2 reuse on logits)
#define SP_PITCH 80
#define SP_AMAT  10240
#define SP_STAGE 40960
#define SP_SMEM  81920

__global__ __launch_bounds__(256, 2)
void gemm_sp(const __nv_bfloat16* __restrict__ Ah, const __nv_bfloat16* __restrict__ Al,
             int lda, const int* __restrict__ gidxA,
             const __nv_bfloat16* __restrict__ Bh, const __nv_bfloat16* __restrict__ Bl,
             int ldb, const int* __restrict__ gidxB,
             float* __restrict__ C, __nv_bfloat16* __restrict__ hiC, __nv_bfloat16* __restrict__ loC,
             size_t ldc, size_t partStride,
             const float* __restrict__ biasM, const float* __restrict__ biasN,
             float* __restrict__ partials, int Nbound, int K, int swapXY)
{
    extern __shared__ __align__(128) char smem[];
    uint32_t sbase = smem_u32(smem);
    int tid = threadIdx.x, wid = tid >> 5, lane = tid & 31;
    int nbx = swapXY ? blockIdx.y : blockIdx.x;
    int nby = swapXY ? blockIdx.x : blockIdx.y;
    int n0 = nbx * 128;
    int m0 = nby * 128;
    int kbase = blockIdx.z * K;
    int wm = (wid >> 2) * 64;
    int wn = (wid & 3) * 32;

    float acc[4][4][4];
    #pragma unroll
    for (int a = 0; a < 4; a++)
        #pragma unroll
        for (int b = 0; b < 4; b++)
            #pragma unroll
            for (int cc = 0; cc < 4; cc++) acc[a][b][cc] = 0.f;

    auto copy_stage = [&](int s, int k0e) {
        uint32_t dst0 = sbase + (uint32_t)s * SP_STAGE;
        int colb = kbase + k0e + (tid & 3) * 8;
        #pragma unroll
        for (int j = 0; j < 8; j++) {
            int c = j * 256 + tid;
            int mat = c >> 9;
            int row = (c >> 2) & 127;
            const __nv_bfloat16* g;
            if (mat < 2) {
                int r = m0 + row;
                if (gidxA) r = gidxA[r];
                g = (mat ? Al : Ah) + (size_t)r * lda + colb;
            } else {
                int r = n0 + row;
                if (gidxB) r = gidxB[r];
                g = ((mat == 3) ? Bl : Bh) + (size_t)r * ldb + colb;
            }
            uint32_t dst = dst0 + (uint32_t)mat * SP_AMAT + (uint32_t)row * SP_PITCH
                         + (uint32_t)(tid & 3) * 16;
            CP_ASYNC16(dst, g);
        }
    };

    int kt = K / 32;
    copy_stage(0, 0);
    CP_COMMIT();

    for (int ki = 0; ki < kt; ki++) {
        int s = ki & 1;
        if (ki + 1 < kt) {
            copy_stage(s ^ 1, (ki + 1) * 32);
            CP_COMMIT();
            CP_WAIT1();
        } else {
            CP_WAIT0();
        }
        __syncthreads();

        uint32_t As  = sbase + (uint32_t)s * SP_STAGE;
        uint32_t Asl = As + SP_AMAT;
        uint32_t Bs  = As + 2 * SP_AMAT;
        uint32_t Bsl = As + 3 * SP_AMAT;

        #pragma unroll
        for (int kb = 0; kb < 32; kb += 16) {
            uint32_t af[4][4], b1[2][4], b2[2][4];
            uint32_t aoff = (uint32_t)(wm + (lane & 15)) * SP_PITCH
                          + (uint32_t)(kb + ((lane >> 4) << 3)) * 2;
            uint32_t boff = (uint32_t)(wn + (lane & 7) + ((lane >> 1) & 8)) * SP_PITCH
                          + (uint32_t)(kb + ((lane >> 3) & 1) * 8) * 2;
            #pragma unroll
            for (int mt = 0; mt < 4; mt++) LDM_X4(af[mt], As + aoff + mt * 16 * SP_PITCH);
            #pragma unroll
            for (int p = 0; p < 2; p++)    LDM_X4(b1[p], Bs + boff + p * 16 * SP_PITCH);
            #pragma unroll
            for (int mt = 0; mt < 4; mt++)
                #pragma unroll
                for (int nt = 0; nt < 4; nt++) {
                    int p = nt >> 1, q = (nt & 1) * 2;
                    MMA16816(acc[mt][nt], af[mt], b1[p][q], b1[p][q + 1]);
                }
            #pragma unroll
            for (int p = 0; p < 2; p++)    LDM_X4(b2[p], Bsl + boff + p * 16 * SP_PITCH);
            #pragma unroll
            for (int mt = 0; mt < 4; mt++)
                #pragma unroll
                for (int nt = 0; nt < 4; nt++) {
                    int p = nt >> 1, q = (nt & 1) * 2;
                    MMA16816(acc[mt][nt], af[mt], b2[p][q], b2[p][q + 1]);
                }
            #pragma unroll
            for (int mt = 0; mt < 4; mt++) LDM_X4(af[mt], Asl + aoff + mt * 16 * SP_PITCH);
            #pragma unroll
            for (int mt = 0; mt < 4; mt++)
                #pragma unroll
                for (int nt = 0; nt < 4; nt++) {
                    int p = nt >> 1, q = (nt & 1) * 2;
                    MMA16816(acc[mt][nt], af[mt], b1[p][q], b1[p][q + 1]);
                }
        }
        __syncthreads();
    }

    // -------- epilogue: stores --------
    #pragma unroll
    for (int mt = 0; mt < 4; mt++)
        #pragma unroll
        for (int nt = 0; nt < 4; nt++) {
            int m = m0 + wm + mt * 16 + (lane >> 2);
            int n = n0 + wn + nt * 8 + (lane & 3) * 2;
            if (n >= Nbound) continue;
            float bm0 = biasM ? biasM[m] : 0.f;
            float bm1 = biasM ? biasM[m + 8] : 0.f;
            float bn0 = biasN ? biasN[n] : 0.f;
            float bn1 = biasN ? biasN[n + 1] : 0.f;
            float v0 = acc[mt][nt][0] + bm0 + bn0;
            float v1 = acc[mt][nt][1] + bm0 + bn1;
            float v2 = acc[mt][nt][2] + bm1 + bn0;
            float v3 = acc[mt][nt][3] + bm1 + bn1;
            if (hiC) {
                __nv_bfloat16 h0 = __float2bfloat16_rn(v0), h1 = __float2bfloat16_rn(v1);
                __nv_bfloat16 h2 = __float2bfloat16_rn(v2), h3 = __float2bfloat16_rn(v3);
                size_t o0 = (size_t)m * ldc + n, o1 = (size_t)(m + 8) * ldc + n;
                *(__nv_bfloat162*)(hiC + o0) = __nv_bfloat162(h0, h1);
                *(__nv_bfloat162*)(hiC + o1) = __nv_bfloat162(h2, h3);
                *(__nv_bfloat162*)(loC + o0) = __nv_bfloat162(
                    __float2bfloat16_rn(v0 - __bfloat162float(h0)),
                    __float2bfloat16_rn(v1 - __bfloat162float(h1)));
                *(__nv_bfloat162*)(loC + o1) = __nv_bfloat162(
                    __float2bfloat16_rn(v2 - __bfloat162float(h2)),
                    __float2bfloat16_rn(v3 - __bfloat162float(h3)));
            } else {
                float* Cp = C + (size_t)blockIdx.z * partStride;
                *(float2*)&Cp[(size_t)m * ldc + n]       = make_float2(v0, v1);
                *(float2*)&Cp[(size_t)(m + 8) * ldc + n] = make_float2(v2, v3);
            }
        }

    // -------- epilogue: fused softmax partials (shuffle-based) --------
    if (partials) {
        float* sred = (float*)smem;              // [128][4] per-warp-band max
        float* ssum = (float*)(smem + 2048);     // [128][4] per-warp-band expsum
        #pragma unroll
        for (int mt = 0; mt < 4; mt++)
            #pragma unroll
            for (int half = 0; half < 2; half++) {
                float vm = -1e30f;
                #pragma unroll
                for (int nt = 0; nt < 4; nt++) {
                    int n = n0 + wn + nt * 8 + (lane & 3) * 2;
                    if (n < Nbound)     vm = fmaxf(vm, acc[mt][nt][half * 2]);
                    if (n + 1 < Nbound) vm = fmaxf(vm, acc[mt][nt][half * 2 + 1]);
                }
                vm = fmaxf(vm, __shfl_xor_sync(0xffffffffu, vm, 1));
                vm = fmaxf(vm, __shfl_xor_sync(0xffffffffu, vm, 2));
                int rl = wm + mt * 16 + (lane >> 2) + half * 8;
                if ((lane & 3) == 0) sred[rl * 4 + (wid & 3)] = vm;
            }
        __syncthreads();
        #pragma unroll
        for (int mt = 0; mt < 4; mt++)
            #pragma unroll
            for (int half = 0; half < 2; half++) {
                int rl = wm + mt * 16 + (lane >> 2) + half * 8;
                float rm = fmaxf(fmaxf(sred[rl * 4 + 0], sred[rl * 4 + 1]),
                                 fmaxf(sred[rl * 4 + 2], sred[rl * 4 + 3]));
                float s = 0.f;
                #pragma unroll
                for (int nt = 0; nt < 4; nt++) {
                    int n = n0 + wn + nt * 8 + (lane & 3) * 2;
                    if (n < Nbound)     s += __expf(acc[mt][nt][half * 2] - rm);
                    if (n + 1 < Nbound) s += __expf(acc[mt][nt][half * 2 + 1] - rm);
                }
                s += __shfl_xor_sync(0xffffffffu, s, 1);
                s += __shfl_xor_sync(0xffffffffu, s, 2);
                if ((lane & 3) == 0) ssum[rl * 4 + (wid & 3)] = s;
            }
        __syncthreads();
        if (tid < 128) {
            float rm = fmaxf(fmaxf(sred[tid * 4 + 0], sred[tid * 4 + 1]),
                             fmaxf(sred[tid * 4 + 2], sred[tid * 4 + 3]));
            float rs = ssum[tid * 4 + 0] + ssum[tid * 4 + 1]
                     + ssum[tid * 4 + 2] + ssum[tid * 4 + 3];
            int gx = swapXY ? gridDim.y : gridDim.x;
            size_t rows = (size_t)(swapXY ? gridDim.x : gridDim.y) * 128;
            partials[(size_t)(m0 + tid) * gx + nbx] = rm;
            partials[rows * gx + (size_t)(m0 + tid) * gx + nbx] = rs;
        }
    }
}

// combine split-K partials: fp32 and/or split bf16 output
__global__ void combine2(const float* __restrict__ p, float* __restrict__ oF,
                         __nv_bfloat16* __restrict__ oH, __nv_bfloat16* __restrict__ oL, int doRelu)
{
    size_t i = ((size_t)blockIdx.x * blockDim.x + threadIdx.x) * 4;
    const float4* a = (const float4*)p;
    float4 v0 = a[i / 4], v1 = a[i / 4 + NH / 4];
    float f[4] = {v0.x + v1.x, v0.y + v1.y, v0.z + v1.z, v0.w + v1.w};
    if (doRelu) {
        #pragma unroll
        for (int j = 0; j < 4; j++) f[j] = fmaxf(f[j], 0.f);
    }
    if (oF) *(float4*)(oF + i) = make_float4(f[0], f[1], f[2], f[3]);
    if (oH) {
        __nv_bfloat16 h[4], l[4];
        #pragma unroll
        for (int j = 0; j < 4; j++) {
            h[j] = __float2bfloat16_rn(f[j]);
            l[j] = __float2bfloat16_rn(f[j] - __bfloat162float(h[j]));
        }
        *(__nv_bfloat162*)(oH + i)     = __nv_bfloat162(h[0], h[1]);
        *(__nv_bfloat162*)(oH + i + 2) = __nv_bfloat162(h[2], h[3]);
        *(__nv_bfloat162*)(oL + i)     = __nv_bfloat162(l[0], l[1]);
        *(__nv_bfloat162*)(oL + i + 2) = __nv_bfloat162(l[2], l[3]);
    }
}

// ---------------- transpose (Wf4 only) ----------------
__global__ void transpose_k(const float* __restrict__ W, float* __restrict__ Wt, int R, int C)
{
    __shared__ float tile[32][33];
    int c0 = blockIdx.x * 32, r0 = blockIdx.y * 32;
    int x = threadIdx.x, y = threadIdx.y;
    #pragma unroll
    for (int dy = 0; dy < 32; dy += 8) {
        int r = r0 + y + dy, c = c0 + x;
        if (r < R && c < C) tile[y + dy][x] = W[(size_t)r * C + c];
    }
    __syncthreads();
    #pragma unroll
    for (int dy = 0; dy < 32; dy += 8) {
        int c = c0 + y + dy, r = r0 + x;
        if (c < C && r < R) Wt[(size_t)c * R + r] = tile[x][y + dy];
    }
}

// ---------------- attention / pooling / softmax ----------------
// 8 nodes per block (grid NNODES/8)
__global__ void alpha_scatter(const float* __restrict__ q1s, const float* __restrict__ q2,
                              const float* __restrict__ z, const float* __restrict__ Wf3,
                              const int* __restrict__ idx, float* __restrict__ sg)
{
    int c = threadIdx.x;
    float w3 = Wf3[c];
    __shared__ float red[8];
    #pragma unroll
    for (int j = 0; j < 8; j++) {
        int n = blockIdx.x * 8 + j;
        int b = idx[n];
        float q = q1s[b * HID + c] + q2[(size_t)n * HID + c];
        float t = w3 / (1.f + __expf(-q));
        #pragma unroll
        for (int o = 16; o > 0; o >>= 1) t += __shfl_xor_sync(0xffffffffu, t, o);
        if ((c & 31) == 0) red[c >> 5] = t;
        __syncthreads();
        float alpha = red[0] + red[1] + red[2] + red[3] + red[4] + red[5] + red[6] + red[7];
        atomicAdd(&sg[b * HID + c], alpha * z[(size_t)n * HID + c]);
        __syncthreads();
    }
}

__global__ void sh_kernel(const float* __restrict__ z, const int* __restrict__ last_item,
                          const float* __restrict__ sg, const float* __restrict__ wf4t,
                          const float* __restrict__ bf4,
                          __nv_bfloat16* __restrict__ shh, __nv_bfloat16* __restrict__ shl)
{
    int b = blockIdx.x, c = threadIdx.x;
    __shared__ float srow[2 * HID];
    int li = last_item[b];
    srow[c]       = z[(size_t)li * HID + c];
    srow[HID + c] = sg[b * HID + c];
    __syncthreads();
    float acc = bf4[c];
    #pragma unroll 8
    for (int k = 0; k < 2 * HID; k++) acc += srow[k] * wf4t[k * HID + c];
    __nv_bfloat16 hh = __float2bfloat16_rn(acc);
    shh[b * HID + c] = hh;
    shl[b * HID + c] = __float2bfloat16_rn(acc - __bfloat162float(hh));
}

// reduce LG_GX (max, expsum) partials per session -> gmax/gsum
__global__ void softmax_combine(const float* __restrict__ part,
                                float* __restrict__ gmax, float* __restrict__ gsum)
{
    int b = blockIdx.x, t = threadIdx.x;
    const float* pm = part + (size_t)b * LG_GX;
    const float* ps = part + (size_t)BSESS * LG_GX + (size_t)b * LG_GX;
    float m = -1e30f, s = 0.f;
    for (int i = t; i < LG_GX; i += 256) {
        float m2 = pm[i], s2 = ps[i];
        float M = fmaxf(m, m2);
        s = s * __expf(m - M) + s2 * __expf(m2 - M);
        m = M;
    }
    __shared__ float sm[256], ss[256];
    sm[t] = m; ss[t] = s;
    __syncthreads();
    for (int o = 128; o > 0; o >>= 1) {
        if (t < o) {
            float m2 = sm[t + o], s2 = ss[t + o];
            float M = fmaxf(sm[t], m2);
            ss[t] = ss[t] * __expf(sm[t] - M) + s2 * __expf(m2 - M);
            sm[t] = M;
        }
        __syncthreads();
    }
    if (t == 0) { gmax[b] = sm[0]; gsum[b] = ss[0]; }
}

__global__ void softmax_write(float* __restrict__ out,
                              const float* __restrict__ gmax, const float* __restrict__ gsum)
{
    int b = blockIdx.y;
    int i4 = blockIdx.x * blockDim.x + threadIdx.x;
    if (i4 * 4 >= NITEMS) return;
    float m = gmax[b], inv = 1.f / gsum[b];
    float4* p = (float4*)(out + (size_t)b * NITEMS) + i4;
    float4 v = *p;
    v.x = __expf(v.x - m) * inv; v.y = __expf(v.y - m) * inv;
    v.z = __expf(v.z - m) * inv; v.w = __expf(v.w - m) * inv;
    *p = v;
}

// ---------------- launcher ----------------
extern "C" void kernel_launch(void* const* d_in, const int* in_sizes, int n_in,
                              void* d_out, int out_size)
{
    const float* adj       = (const float*)d_in[0];
    const int*   items     = (const int*)  d_in[1];
    const int*   last_item = (const int*)  d_in[2];
    const int*   idx       = (const int*)  d_in[3];
    const float* emb       = (const float*)d_in[4];
    const float* W1  = (const float*)d_in[5];
    const float* b1  = (const float*)d_in[6];
    const float* W2  = (const float*)d_in[7];
    const float* b2  = (const float*)d_in[8];
    const float* Wf1 = (const float*)d_in[9];
    const float* bf1 = (const float*)d_in[10];
    const float* Wf2 = (const float*)d_in[11];
    const float* bf2 = (const float*)d_in[12];
    const float* Wf3 = (const float*)d_in[13];
    const float* Wf4 = (const float*)d_in[14];
    const float* bf4 = (const float*)d_in[15];
    float* out = (float*)d_out;

    float* fb = nullptr;
    cudaGetSymbolAddress((void**)&fb, g_f);
    float* z    = fb + F_Z;
    float* q2   = fb + F_Q2;
    float* part = fb + F_P;
    float* q1s  = fb + F_Q1S;
    float* sg   = fb + F_SG;
    float* wf4t = fb + F_WF4T;
    float* gmax = fb + F_MAX;
    float* gsum = fb + F_SUM;

    __nv_bfloat16 *adjh, *adjl, *embh, *embl, *xh, *xl, *hh, *hl, *zh, *zl, *shh, *shl;
    __nv_bfloat16 *w1h, *w1l, *w2h, *w2l, *wf1h, *wf1l, *wf2h, *wf2l;
    cudaGetSymbolAddress((void**)&adjh, g_adj_h);
    cudaGetSymbolAddress((void**)&adjl, g_adj_l);
    cudaGetSymbolAddress((void**)&embh, g_emb_h);
    cudaGetSymbolAddress((void**)&embl, g_emb_l);
    cudaGetSymbolAddress((void**)&xh,   g_x_h);
    cudaGetSymbolAddress((void**)&xl,   g_x_l);
    cudaGetSymbolAddress((void**)&hh,   g_h_h);
    cudaGetSymbolAddress((void**)&hl,   g_h_l);
    cudaGetSymbolAddress((void**)&zh,   g_z_h);
    cudaGetSymbolAddress((void**)&zl,   g_z_l);
    cudaGetSymbolAddress((void**)&shh,  g_sh_h);
    cudaGetSymbolAddress((void**)&shl,  g_sh_l);
    cudaGetSymbolAddress((void**)&w1h,  g_w1h);  cudaGetSymbolAddress((void**)&w1l,  g_w1l);
    cudaGetSymbolAddress((void**)&w2h,  g_w2h);  cudaGetSymbolAddress((void**)&w2l,  g_w2l);
    cudaGetSymbolAddress((void**)&wf1h, g_wf1h); cudaGetSymbolAddress((void**)&wf1l, g_wf1l);
    cudaGetSymbolAddress((void**)&wf2h, g_wf2h); cudaGetSymbolAddress((void**)&wf2l, g_wf2l);

    static bool inited = false;
    if (!inited) {
        cudaFuncSetAttribute(gemm_sp, cudaFuncAttributeMaxDynamicSharedMemorySize, SP_SMEM);
        inited = true;
    }

    // prep: weight splits (one launch), Wf4 transpose, sg zero (memset node), big splits
    cvt_split4<<<dim3(16, 4), 256>>>(W1, W2, Wf1, Wf2,
                                     w1h, w1l, w2h, w2l, wf1h, wf1l, wf2h, wf2l);
    transpose_k<<<dim3(16, 8), dim3(32, 8)>>>(Wf4, wf4t, HID, 2 * HID);
    cudaMemsetAsync(sg, 0, (size_t)BSESS * HID * sizeof(float));
    cvt_split<<<2048, 256>>>(adj, adjh, adjl, (size_t)NNODES * NNODES, (size_t)NNODES * NNODES);
    cvt_split<<<1024, 256>>>(emb, embh, embl, (size_t)NITEMS * HID, (size_t)NITEMS_PAD * HID);

    // t1^T[hid][node] = W1 @ emb[items]^T + b1  (split output xh/xl)
    gemm_sp<<<dim3(64, 2, 1), 256, SP_SMEM>>>(w1h, w1l, HID, nullptr,
                                              embh, embl, HID, items,
                                              nullptr, xh, xl, NNODES, 0,
                                              b1, nullptr, nullptr, NNODES, HID, 0);
    // h = relu(adj @ t1): split-K x2 -> split bf16 hh/hl
    gemm_sp<<<dim3(2, 64, 2), 256, SP_SMEM>>>(adjh, adjl, NNODES, nullptr,
                                              xh, xl, NNODES, nullptr,
                                              part, nullptr, nullptr, HID, NH,
                                              nullptr, nullptr, nullptr, HID, NNODES / 2, 0);
    combine2<<<NH / 1024, 256>>>(part, nullptr, hh, hl, 1);
    // t2^T = W2 @ h^T + b2
    gemm_sp<<<dim3(64, 2, 1), 256, SP_SMEM>>>(w2h, w2l, HID, nullptr,
                                              hh, hl, HID, nullptr,
                                              nullptr, xh, xl, NNODES, 0,
                                              b2, nullptr, nullptr, NNODES, HID, 0);
    // z = adj @ t2 -> z fp32 + zh/zl
    gemm_sp<<<dim3(2, 64, 2), 256, SP_SMEM>>>(adjh, adjl, NNODES, nullptr,
                                              xh, xl, NNODES, nullptr,
                                              part, nullptr, nullptr, HID, NH,
                                              nullptr, nullptr, nullptr, HID, NNODES / 2, 0);
    combine2<<<NH / 1024, 256>>>(part, z, zh, zl, 0);
    // q1s = z[last_item] @ Wf1^T + bf1
    gemm_sp<<<dim3(2, 4, 1), 256, SP_SMEM>>>(zh, zl, HID, last_item,
                                             wf1h, wf1l, HID, nullptr,
                                             q1s, nullptr, nullptr, HID, 0,
                                             nullptr, bf1, nullptr, HID, HID, 0);
    // q2 = z @ Wf2^T + bf2
    gemm_sp<<<dim3(2, 64, 1), 256, SP_SMEM>>>(zh, zl, HID, nullptr,
                                              wf2h, wf2l, HID, nullptr,
                                              q2, nullptr, nullptr, HID, 0,
                                              nullptr, bf2, nullptr, HID, HID, 0);
    alpha_scatter<<<NNODES / 8, 256>>>(q1s, q2, z, Wf3, idx, sg);
    sh_kernel<<<BSESS, 256>>>(z, last_item, sg, wf4t, bf4, shh, shl);
    // logits: out[b][i] = sh[b,:] . emb[i,:], swapped grid (m from x, n from y)
    // so the 4 session-tiles sharing an emb tile are schedule-adjacent -> L2 reuse
    gemm_sp<<<dim3(4, LG_GX, 1), 256, SP_SMEM>>>(shh, shl, HID, nullptr,
                                                 embh, embl, HID, nullptr,
                                                 out, nullptr, nullptr, NITEMS, 0,
                                                 nullptr, nullptr, part, NITEMS, HID, 1);
    softmax_combine<<<BSESS, 256>>>(part, gmax, gsum);
    softmax_write<<<dim3((NITEMS / 4 + 255) / 256, BSESS), 256>>>(out, gmax, gsum);
}

// round 17
// speedup vs baseline: 1.6900x; 1.0051x over previous
#include <cuda_runtime.h>
#include <cuda_bf16.h>
#include <math.h>
#include <stdint.h>

#define HID 256
#define NNODES 8192
#define BSESS 512
#define NITEMS 100000
#define NITEMS_PAD 100096           // 782 * 128
#define LG_GX 782

// ---------------- static scratch (floats) ----------------
constexpr size_t NH = (size_t)NNODES * HID;
constexpr size_t F_Z    = 0;
constexpr size_t F_Q2   = F_Z   + NH;
constexpr size_t F_P    = F_Q2  + NH;                 // 2 x NH partials (also softmax partials)
constexpr size_t F_Q1S  = F_P   + 2 * NH;
constexpr size_t F_SG   = F_Q1S + (size_t)BSESS * HID;
constexpr size_t F_WF4T = F_SG  + (size_t)BSESS * HID;
constexpr size_t F_MAX  = F_WF4T + (size_t)2 * HID * HID;
constexpr size_t F_SUM  = F_MAX + BSESS;
constexpr size_t F_TOTAL = F_SUM + BSESS;
__device__ float g_f[F_TOTAL];

// bf16 hi/lo split buffers
__device__ __nv_bfloat16 g_adj_h[(size_t)NNODES * NNODES];
__device__ __nv_bfloat16 g_adj_l[(size_t)NNODES * NNODES];
__device__ __nv_bfloat16 g_emb_h[(size_t)NITEMS_PAD * HID];
__device__ __nv_bfloat16 g_emb_l[(size_t)NITEMS_PAD * HID];
__device__ __nv_bfloat16 g_x_h[(size_t)HID * NNODES];
__device__ __nv_bfloat16 g_x_l[(size_t)HID * NNODES];
__device__ __nv_bfloat16 g_h_h[NH], g_h_l[NH];
__device__ __nv_bfloat16 g_z_h[NH], g_z_l[NH];
__device__ __nv_bfloat16 g_sh_h[(size_t)BSESS * HID];
__device__ __nv_bfloat16 g_sh_l[(size_t)BSESS * HID];
__device__ __nv_bfloat16 g_w1h[65536], g_w1l[65536];
__device__ __nv_bfloat16 g_w2h[65536], g_w2l[65536];
__device__ __nv_bfloat16 g_wf1h[65536], g_wf1l[65536];
__device__ __nv_bfloat16 g_wf2h[65536], g_wf2l[65536];

// ---------------- PTX helpers ----------------
__device__ __forceinline__ uint32_t smem_u32(const void* p) {
    uint32_t a;
    asm("{ .reg .u64 t; cvta.to.shared.u64 t, %1; cvt.u32.u64 %0, t; }" : "=r"(a) : "l"(p));
    return a;
}
#define LDM_X4(r, a) \
    asm volatile("ldmatrix.sync.aligned.m8n8.x4.shared.b16 {%0,%1,%2,%3}, [%4];" \
        : "=r"((r)[0]), "=r"((r)[1]), "=r"((r)[2]), "=r"((r)[3]) : "r"(a))
#define MMA16816(c, a, b0, b1) \
    asm volatile("mma.sync.aligned.m16n8k16.row.col.f32.bf16.bf16.f32 " \
        "{%0,%1,%2,%3}, {%4,%5,%6,%7}, {%8,%9}, {%0,%1,%2,%3};" \
        : "+f"((c)[0]), "+f"((c)[1]), "+f"((c)[2]), "+f"((c)[3]) \
        : "r"((a)[0]), "r"((a)[1]), "r"((a)[2]), "r"((a)[3]), "r"(b0), "r"(b1))
#define CP_ASYNC16(dst, src) \
    asm volatile("cp.async.cg.shared.global [%0], [%1], 16;" :: "r"(dst), "l"(src) : "memory")
#define CP_COMMIT() asm volatile("cp.async.commit_group;" ::: "memory")
#define CP_WAIT1()  asm volatile("cp.async.wait_group 1;" ::: "memory")
#define CP_WAIT0()  asm volatile("cp.async.wait_group 0;" ::: "memory")

// ---------------- fp32 -> bf16 hi/lo split (generic) ----------------
__global__ void cvt_split(const float* __restrict__ src, __nv_bfloat16* __restrict__ hi,
                          __nv_bfloat16* __restrict__ lo, size_t nsrc, size_t ntot)
{
    size_t stride = (size_t)gridDim.x * blockDim.x;
    for (size_t t = (size_t)blockIdx.x * blockDim.x + threadIdx.x; t * 4 < ntot; t += stride) {
        size_t i = t * 4;
        float4 v = (i < nsrc) ? *(const float4*)(src + i) : make_float4(0.f, 0.f, 0.f, 0.f);
        float f[4] = {v.x, v.y, v.z, v.w};
        __nv_bfloat16 h[4], l[4];
        #pragma unroll
        for (int j = 0; j < 4; j++) {
            h[j] = __float2bfloat16_rn(f[j]);
            l[j] = __float2bfloat16_rn(f[j] - __bfloat162float(h[j]));
        }
        *(__nv_bfloat162*)(hi + i)     = __nv_bfloat162(h[0], h[1]);
        *(__nv_bfloat162*)(hi + i + 2) = __nv_bfloat162(h[2], h[3]);
        *(__nv_bfloat162*)(lo + i)     = __nv_bfloat162(l[0], l[1]);
        *(__nv_bfloat162*)(lo + i + 2) = __nv_bfloat162(l[2], l[3]);
    }
}

// 4 weight matrices (256x256 each) in one launch; blockIdx.y picks the matrix
__global__ void cvt_split4(const float* __restrict__ W1, const float* __restrict__ W2,
                           const float* __restrict__ Wf1, const float* __restrict__ Wf2,
                           __nv_bfloat16* __restrict__ h1, __nv_bfloat16* __restrict__ l1,
                           __nv_bfloat16* __restrict__ h2, __nv_bfloat16* __restrict__ l2,
                           __nv_bfloat16* __restrict__ h3, __nv_bfloat16* __restrict__ l3,
                           __nv_bfloat16* __restrict__ h4, __nv_bfloat16* __restrict__ l4)
{
    int m = blockIdx.y;
    const float* src = (m == 0) ? W1 : (m == 1) ? W2 : (m == 2) ? Wf1 : Wf2;
    __nv_bfloat16* hi = (m == 0) ? h1 : (m == 1) ? h2 : (m == 2) ? h3 : h4;
    __nv_bfloat16* lo = (m == 0) ? l1 : (m == 1) ? l2 : (m == 2) ? l3 : l4;
    size_t stride = (size_t)gridDim.x * blockDim.x;
    for (size_t t = (size_t)blockIdx.x * blockDim.x + threadIdx.x; t * 4 < 65536; t += stride) {
        size_t i = t * 4;
        float4 v = *(const float4*)(src + i);
        float f[4] = {v.x, v.y, v.z, v.w};
        __nv_bfloat16 h[4], l[4];
        #pragma unroll
        for (int j = 0; j < 4; j++) {
            h[j] = __float2bfloat16_rn(f[j]);
            l[j] = __float2bfloat16_rn(f[j] - __bfloat162float(h[j]));
        }
        *(__nv_bfloat162*)(hi + i)     = __nv_bfloat162(h[0], h[1]);
        *(__nv_bfloat162*)(hi + i + 2) = __nv_bfloat162(h[2], h[3]);
        *(__nv_bfloat162*)(lo + i)     = __nv_bfloat162(l[0], l[1]);
        *(__nv_bfloat162*)(lo + i + 2) = __nv_bfloat162(l[2], l[3]);
    }
}

// ---------------- bf16-split GEMM, BM=128 x BN=128, BK=32, 2 stages, occ 2 ----------------
// swapXY: m0 from blockIdx.x, n0 from blockIdx.y (for B-tile L2 reuse on logits)
#define SP_PITCH 80
#define SP_AMAT  10240
#define SP_STAGE 40960
#define SP_SMEM  81920

__global__ __launch_bounds__(256, 2)
void gemm_sp(const __nv_bfloat16* __restrict__ Ah, const __nv_bfloat16* __restrict__ Al,
             int lda, const int* __restrict__ gidxA,
             const __nv_bfloat16* __restrict__ Bh, const __nv_bfloat16* __restrict__ Bl,
             int ldb, const int* __restrict__ gidxB,
             float* __restrict__ C, __nv_bfloat16* __restrict__ hiC, __nv_bfloat16* __restrict__ loC,
             size_t ldc, size_t partStride,
             const float* __restrict__ biasM, const float* __restrict__ biasN,
             float* __restrict__ partials, int Nbound, int K, int swapXY)
{
    extern __shared__ __align__(128) char smem[];
    uint32_t sbase = smem_u32(smem);
    int tid = threadIdx.x, wid = tid >> 5, lane = tid & 31;
    int nbx = swapXY ? blockIdx.y : blockIdx.x;
    int nby = swapXY ? blockIdx.x : blockIdx.y;
    int n0 = nbx * 128;
    int m0 = nby * 128;
    int kbase = blockIdx.z * K;
    int wm = (wid >> 2) * 64;
    int wn = (wid & 3) * 32;

    float acc[4][4][4];
    #pragma unroll
    for (int a = 0; a < 4; a++)
        #pragma unroll
        for (int b = 0; b < 4; b++)
            #pragma unroll
            for (int cc = 0; cc < 4; cc++) acc[a][b][cc] = 0.f;

    auto copy_stage = [&](int s, int k0e) {
        uint32_t dst0 = sbase + (uint32_t)s * SP_STAGE;
        int colb = kbase + k0e + (tid & 3) * 8;
        #pragma unroll
        for (int j = 0; j < 8; j++) {
            int c = j * 256 + tid;
            int mat = c >> 9;
            int row = (c >> 2) & 127;
            const __nv_bfloat16* g;
            if (mat < 2) {
                int r = m0 + row;
                if (gidxA) r = gidxA[r];
                g = (mat ? Al : Ah) + (size_t)r * lda + colb;
            } else {
                int r = n0 + row;
                if (gidxB) r = gidxB[r];
                g = ((mat == 3) ? Bl : Bh) + (size_t)r * ldb + colb;
            }
            uint32_t dst = dst0 + (uint32_t)mat * SP_AMAT + (uint32_t)row * SP_PITCH
                         + (uint32_t)(tid & 3) * 16;
            CP_ASYNC16(dst, g);
        }
    };

    int kt = K / 32;
    copy_stage(0, 0);
    CP_COMMIT();

    for (int ki = 0; ki < kt; ki++) {
        int s = ki & 1;
        if (ki + 1 < kt) {
            copy_stage(s ^ 1, (ki + 1) * 32);
            CP_COMMIT();
            CP_WAIT1();
        } else {
            CP_WAIT0();
        }
        __syncthreads();

        uint32_t As  = sbase + (uint32_t)s * SP_STAGE;
        uint32_t Asl = As + SP_AMAT;
        uint32_t Bs  = As + 2 * SP_AMAT;
        uint32_t Bsl = As + 3 * SP_AMAT;

        #pragma unroll
        for (int kb = 0; kb < 32; kb += 16) {
            uint32_t af[4][4], b1[2][4], b2[2][4];
            uint32_t aoff = (uint32_t)(wm + (lane & 15)) * SP_PITCH
                          + (uint32_t)(kb + ((lane >> 4) << 3)) * 2;
            uint32_t boff = (uint32_t)(wn + (lane & 7) + ((lane >> 1) & 8)) * SP_PITCH
                          + (uint32_t)(kb + ((lane >> 3) & 1) * 8) * 2;
            #pragma unroll
            for (int mt = 0; mt < 4; mt++) LDM_X4(af[mt], As + aoff + mt * 16 * SP_PITCH);
            #pragma unroll
            for (int p = 0; p < 2; p++)    LDM_X4(b1[p], Bs + boff + p * 16 * SP_PITCH);
            #pragma unroll
            for (int mt = 0; mt < 4; mt++)
                #pragma unroll
                for (int nt = 0; nt < 4; nt++) {
                    int p = nt >> 1, q = (nt & 1) * 2;
                    MMA16816(acc[mt][nt], af[mt], b1[p][q], b1[p][q + 1]);
                }
            #pragma unroll
            for (int p = 0; p < 2; p++)    LDM_X4(b2[p], Bsl + boff + p * 16 * SP_PITCH);
            #pragma unroll
            for (int mt = 0; mt < 4; mt++)
                #pragma unroll
                for (int nt = 0; nt < 4; nt++) {
                    int p = nt >> 1, q = (nt & 1) * 2;
                    MMA16816(acc[mt][nt], af[mt], b2[p][q], b2[p][q + 1]);
                }
            #pragma unroll
            for (int mt = 0; mt < 4; mt++) LDM_X4(af[mt], Asl + aoff + mt * 16 * SP_PITCH);
            #pragma unroll
            for (int mt = 0; mt < 4; mt++)
                #pragma unroll
                for (int nt = 0; nt < 4; nt++) {
                    int p = nt >> 1, q = (nt & 1) * 2;
                    MMA16816(acc[mt][nt], af[mt], b1[p][q], b1[p][q + 1]);
                }
        }
        __syncthreads();
    }

    // -------- epilogue: stores --------
    #pragma unroll
    for (int mt = 0; mt < 4; mt++)
        #pragma unroll
        for (int nt = 0; nt < 4; nt++) {
            int m = m0 + wm + mt * 16 + (lane >> 2);
            int n = n0 + wn + nt * 8 + (lane & 3) * 2;
            if (n >= Nbound) continue;
            float bm0 = biasM ? biasM[m] : 0.f;
            float bm1 = biasM ? biasM[m + 8] : 0.f;
            float bn0 = biasN ? biasN[n] : 0.f;
            float bn1 = biasN ? biasN[n + 1] : 0.f;
            float v0 = acc[mt][nt][0] + bm0 + bn0;
            float v1 = acc[mt][nt][1] + bm0 + bn1;
            float v2 = acc[mt][nt][2] + bm1 + bn0;
            float v3 = acc[mt][nt][3] + bm1 + bn1;
            if (hiC) {
                __nv_bfloat16 h0 = __float2bfloat16_rn(v0), h1 = __float2bfloat16_rn(v1);
                __nv_bfloat16 h2 = __float2bfloat16_rn(v2), h3 = __float2bfloat16_rn(v3);
                size_t o0 = (size_t)m * ldc + n, o1 = (size_t)(m + 8) * ldc + n;
                *(__nv_bfloat162*)(hiC + o0) = __nv_bfloat162(h0, h1);
                *(__nv_bfloat162*)(hiC + o1) = __nv_bfloat162(h2, h3);
                *(__nv_bfloat162*)(loC + o0) = __nv_bfloat162(
                    __float2bfloat16_rn(v0 - __bfloat162float(h0)),
                    __float2bfloat16_rn(v1 - __bfloat162float(h1)));
                *(__nv_bfloat162*)(loC + o1) = __nv_bfloat162(
                    __float2bfloat16_rn(v2 - __bfloat162float(h2)),
                    __float2bfloat16_rn(v3 - __bfloat162float(h3)));
            } else {
                float* Cp = C + (size_t)blockIdx.z * partStride;
                *(float2*)&Cp[(size_t)m * ldc + n]       = make_float2(v0, v1);
                *(float2*)&Cp[(size_t)(m + 8) * ldc + n] = make_float2(v2, v3);
            }
        }

    // -------- epilogue: fused softmax partials (shuffle-based) --------
    if (partials) {
        float* sred = (float*)smem;              // [128][4] per-warp-band max
        float* ssum = (float*)(smem + 2048);     // [128][4] per-warp-band expsum
        #pragma unroll
        for (int mt = 0; mt < 4; mt++)
            #pragma unroll
            for (int half = 0; half < 2; half++) {
                float vm = -1e30f;
                #pragma unroll
                for (int nt = 0; nt < 4; nt++) {
                    int n = n0 + wn + nt * 8 + (lane & 3) * 2;
                    if (n < Nbound)     vm = fmaxf(vm, acc[mt][nt][half * 2]);
                    if (n + 1 < Nbound) vm = fmaxf(vm, acc[mt][nt][half * 2 + 1]);
                }
                vm = fmaxf(vm, __shfl_xor_sync(0xffffffffu, vm, 1));
                vm = fmaxf(vm, __shfl_xor_sync(0xffffffffu, vm, 2));
                int rl = wm + mt * 16 + (lane >> 2) + half * 8;
                if ((lane & 3) == 0) sred[rl * 4 + (wid & 3)] = vm;
            }
        __syncthreads();
        #pragma unroll
        for (int mt = 0; mt < 4; mt++)
            #pragma unroll
            for (int half = 0; half < 2; half++) {
                int rl = wm + mt * 16 + (lane >> 2) + half * 8;
                float rm = fmaxf(fmaxf(sred[rl * 4 + 0], sred[rl * 4 + 1]),
                                 fmaxf(sred[rl * 4 + 2], sred[rl * 4 + 3]));
                float s = 0.f;
                #pragma unroll
                for (int nt = 0; nt < 4; nt++) {
                    int n = n0 + wn + nt * 8 + (lane & 3) * 2;
                    if (n < Nbound)     s += __expf(acc[mt][nt][half * 2] - rm);
                    if (n + 1 < Nbound) s += __expf(acc[mt][nt][half * 2 + 1] - rm);
                }
                s += __shfl_xor_sync(0xffffffffu, s, 1);
                s += __shfl_xor_sync(0xffffffffu, s, 2);
                if ((lane & 3) == 0) ssum[rl * 4 + (wid & 3)] = s;
            }
        __syncthreads();
        if (tid < 128) {
            float rm = fmaxf(fmaxf(sred[tid * 4 + 0], sred[tid * 4 + 1]),
                             fmaxf(sred[tid * 4 + 2], sred[tid * 4 + 3]));
            float rs = ssum[tid * 4 + 0] + ssum[tid * 4 + 1]
                     + ssum[tid * 4 + 2] + ssum[tid * 4 + 3];
            int gx = swapXY ? gridDim.y : gridDim.x;
            size_t rows = (size_t)(swapXY ? gridDim.x : gridDim.y) * 128;
            partials[(size_t)(m0 + tid) * gx + nbx] = rm;
            partials[rows * gx + (size_t)(m0 + tid) * gx + nbx] = rs;
        }
    }
}

// combine split-K partials: fp32 and/or split bf16 output
__global__ void combine2(const float* __restrict__ p, float* __restrict__ oF,
                         __nv_bfloat16* __restrict__ oH, __nv_bfloat16* __restrict__ oL, int doRelu)
{
    size_t i = ((size_t)blockIdx.x * blockDim.x + threadIdx.x) * 4;
    const float4* a = (const float4*)p;
    float4 v0 = a[i / 4], v1 = a[i / 4 + NH / 4];
    float f[4] = {v0.x + v1.x, v0.y + v1.y, v0.z + v1.z, v0.w + v1.w};
    if (doRelu) {
        #pragma unroll
        for (int j = 0; j < 4; j++) f[j] = fmaxf(f[j], 0.f);
    }
    if (oF) *(float4*)(oF + i) = make_float4(f[0], f[1], f[2], f[3]);
    if (oH) {
        __nv_bfloat16 h[4], l[4];
        #pragma unroll
        for (int j = 0; j < 4; j++) {
            h[j] = __float2bfloat16_rn(f[j]);
            l[j] = __float2bfloat16_rn(f[j] - __bfloat162float(h[j]));
        }
        *(__nv_bfloat162*)(oH + i)     = __nv_bfloat162(h[0], h[1]);
        *(__nv_bfloat162*)(oH + i + 2) = __nv_bfloat162(h[2], h[3]);
        *(__nv_bfloat162*)(oL + i)     = __nv_bfloat162(l[0], l[1]);
        *(__nv_bfloat162*)(oL + i + 2) = __nv_bfloat162(l[2], l[3]);
    }
}

// ---------------- transpose (Wf4 only) ----------------
__global__ void transpose_k(const float* __restrict__ W, float* __restrict__ Wt, int R, int C)
{
    __shared__ float tile[32][33];
    int c0 = blockIdx.x * 32, r0 = blockIdx.y * 32;
    int x = threadIdx.x, y = threadIdx.y;
    #pragma unroll
    for (int dy = 0; dy < 32; dy += 8) {
        int r = r0 + y + dy, c = c0 + x;
        if (r < R && c < C) tile[y + dy][x] = W[(size_t)r * C + c];
    }
    __syncthreads();
    #pragma unroll
    for (int dy = 0; dy < 32; dy += 8) {
        int c = c0 + y + dy, r = r0 + x;
        if (c < C && r < R) Wt[(size_t)c * R + r] = tile[x][y + dy];
    }
}

// ---------------- attention / pooling / softmax ----------------
// 8 nodes per block (grid NNODES/8)
__global__ void alpha_scatter(const float* __restrict__ q1s, const float* __restrict__ q2,
                              const float* __restrict__ z, const float* __restrict__ Wf3,
                              const int* __restrict__ idx, float* __restrict__ sg)
{
    int c = threadIdx.x;
    float w3 = Wf3[c];
    __shared__ float red[8];
    #pragma unroll
    for (int j = 0; j < 8; j++) {
        int n = blockIdx.x * 8 + j;
        int b = idx[n];
        float q = q1s[b * HID + c] + q2[(size_t)n * HID + c];
        float t = w3 / (1.f + __expf(-q));
        #pragma unroll
        for (int o = 16; o > 0; o >>= 1) t += __shfl_xor_sync(0xffffffffu, t, o);
        if ((c & 31) == 0) red[c >> 5] = t;
        __syncthreads();
        float alpha = red[0] + red[1] + red[2] + red[3] + red[4] + red[5] + red[6] + red[7];
        atomicAdd(&sg[b * HID + c], alpha * z[(size_t)n * HID + c]);
        __syncthreads();
    }
}

__global__ void sh_kernel(const float* __restrict__ z, const int* __restrict__ last_item,
                          const float* __restrict__ sg, const float* __restrict__ wf4t,
                          const float* __restrict__ bf4,
                          __nv_bfloat16* __restrict__ shh, __nv_bfloat16* __restrict__ shl)
{
    int b = blockIdx.x, c = threadIdx.x;
    __shared__ float srow[2 * HID];
    int li = last_item[b];
    srow[c]       = z[(size_t)li * HID + c];
    srow[HID + c] = sg[b * HID + c];
    __syncthreads();
    float acc = bf4[c];
    #pragma unroll 8
    for (int k = 0; k < 2 * HID; k++) acc += srow[k] * wf4t[k * HID + c];
    __nv_bfloat16 hh = __float2bfloat16_rn(acc);
    shh[b * HID + c] = hh;
    shl[b * HID + c] = __float2bfloat16_rn(acc - __bfloat162float(hh));
}

// reduce LG_GX (max, expsum) partials per session -> gmax/gsum
__global__ void softmax_combine(const float* __restrict__ part,
                                float* __restrict__ gmax, float* __restrict__ gsum)
{
    int b = blockIdx.x, t = threadIdx.x;
    const float* pm = part + (size_t)b * LG_GX;
    const float* ps = part + (size_t)BSESS * LG_GX + (size_t)b * LG_GX;
    float m = -1e30f, s = 0.f;
    for (int i = t; i < LG_GX; i += 256) {
        float m2 = pm[i], s2 = ps[i];
        float M = fmaxf(m, m2);
        s = s * __expf(m - M) + s2 * __expf(m2 - M);
        m = M;
    }
    __shared__ float sm[256], ss[256];
    sm[t] = m; ss[t] = s;
    __syncthreads();
    for (int o = 128; o > 0; o >>= 1) {
        if (t < o) {
            float m2 = sm[t + o], s2 = ss[t + o];
            float M = fmaxf(sm[t], m2);
            ss[t] = ss[t] * __expf(sm[t] - M) + s2 * __expf(m2 - M);
            sm[t] = M;
        }
        __syncthreads();
    }
    if (t == 0) { gmax[b] = sm[0]; gsum[b] = ss[0]; }
}

__global__ void softmax_write(float* __restrict__ out,
                              const float* __restrict__ gmax, const float* __restrict__ gsum)
{
    int b = blockIdx.y;
    int i4 = blockIdx.x * blockDim.x + threadIdx.x;
    if (i4 * 4 >= NITEMS) return;
    float m = gmax[b], inv = 1.f / gsum[b];
    float4* p = (float4*)(out + (size_t)b * NITEMS) + i4;
    float4 v = *p;
    v.x = __expf(v.x - m) * inv; v.y = __expf(v.y - m) * inv;
    v.z = __expf(v.z - m) * inv; v.w = __expf(v.w - m) * inv;
    *p = v;
}

// ---------------- launcher ----------------
extern "C" void kernel_launch(void* const* d_in, const int* in_sizes, int n_in,
                              void* d_out, int out_size)
{
    const float* adj       = (const float*)d_in[0];
    const int*   items     = (const int*)  d_in[1];
    const int*   last_item = (const int*)  d_in[2];
    const int*   idx       = (const int*)  d_in[3];
    const float* emb       = (const float*)d_in[4];
    const float* W1  = (const float*)d_in[5];
    const float* b1  = (const float*)d_in[6];
    const float* W2  = (const float*)d_in[7];
    const float* b2  = (const float*)d_in[8];
    const float* Wf1 = (const float*)d_in[9];
    const float* bf1 = (const float*)d_in[10];
    const float* Wf2 = (const float*)d_in[11];
    const float* bf2 = (const float*)d_in[12];
    const float* Wf3 = (const float*)d_in[13];
    const float* Wf4 = (const float*)d_in[14];
    const float* bf4 = (const float*)d_in[15];
    float* out = (float*)d_out;

    float* fb = nullptr;
    cudaGetSymbolAddress((void**)&fb, g_f);
    float* z    = fb + F_Z;
    float* q2   = fb + F_Q2;
    float* part = fb + F_P;
    float* q1s  = fb + F_Q1S;
    float* sg   = fb + F_SG;
    float* wf4t = fb + F_WF4T;
    float* gmax = fb + F_MAX;
    float* gsum = fb + F_SUM;

    __nv_bfloat16 *adjh, *adjl, *embh, *embl, *xh, *xl, *hh, *hl, *zh, *zl, *shh, *shl;
    __nv_bfloat16 *w1h, *w1l, *w2h, *w2l, *wf1h, *wf1l, *wf2h, *wf2l;
    cudaGetSymbolAddress((void**)&adjh, g_adj_h);
    cudaGetSymbolAddress((void**)&adjl, g_adj_l);
    cudaGetSymbolAddress((void**)&embh, g_emb_h);
    cudaGetSymbolAddress((void**)&embl, g_emb_l);
    cudaGetSymbolAddress((void**)&xh,   g_x_h);
    cudaGetSymbolAddress((void**)&xl,   g_x_l);
    cudaGetSymbolAddress((void**)&hh,   g_h_h);
    cudaGetSymbolAddress((void**)&hl,   g_h_l);
    cudaGetSymbolAddress((void**)&zh,   g_z_h);
    cudaGetSymbolAddress((void**)&zl,   g_z_l);
    cudaGetSymbolAddress((void**)&shh,  g_sh_h);
    cudaGetSymbolAddress((void**)&shl,  g_sh_l);
    cudaGetSymbolAddress((void**)&w1h,  g_w1h);  cudaGetSymbolAddress((void**)&w1l,  g_w1l);
    cudaGetSymbolAddress((void**)&w2h,  g_w2h);  cudaGetSymbolAddress((void**)&w2l,  g_w2l);
    cudaGetSymbolAddress((void**)&wf1h, g_wf1h); cudaGetSymbolAddress((void**)&wf1l, g_wf1l);
    cudaGetSymbolAddress((void**)&wf2h, g_wf2h); cudaGetSymbolAddress((void**)&wf2l, g_wf2l);

    static cudaStream_t s2 = nullptr;
    static cudaEvent_t evFork = nullptr, evA1 = nullptr, evT1 = nullptr, evH0 = nullptr;
    if (!s2) {
        cudaFuncSetAttribute(gemm_sp, cudaFuncAttributeMaxDynamicSharedMemorySize, SP_SMEM);
        cudaStreamCreate(&s2);
        cudaEventCreateWithFlags(&evFork, cudaEventDisableTiming);
        cudaEventCreateWithFlags(&evA1,   cudaEventDisableTiming);
        cudaEventCreateWithFlags(&evT1,   cudaEventDisableTiming);
        cudaEventCreateWithFlags(&evH0,   cudaEventDisableTiming);
    }

    constexpr size_t ADJ_HALF = (size_t)(NNODES / 2) * NNODES;   // rows 0..4095 flat

    // ---- fork: s2 branches off stream 0 ----
    cudaEventRecord(evFork, 0);
    cudaStreamWaitEvent(s2, evFork, 0);

    // stream 0: adj split in two row-halves (DRAM-bound)
    cvt_split<<<1024, 256, 0, 0>>>(adj, adjh, adjl, ADJ_HALF, ADJ_HALF);
    cudaEventRecord(evA1, 0);
    cvt_split<<<1024, 256, 0, 0>>>(adj + ADJ_HALF, adjh + ADJ_HALF, adjl + ADJ_HALF,
                                   ADJ_HALF, ADJ_HALF);

    // stream s2: weights, Wf4^T, sg memset, emb split, t1 GEMM (tensor-bound)
    cvt_split4<<<dim3(16, 4), 256, 0, s2>>>(W1, W2, Wf1, Wf2,
                                            w1h, w1l, w2h, w2l, wf1h, wf1l, wf2h, wf2l);
    transpose_k<<<dim3(16, 8), dim3(32, 8), 0, s2>>>(Wf4, wf4t, HID, 2 * HID);
    cudaMemsetAsync(sg, 0, (size_t)BSESS * HID * sizeof(float), s2);
    cvt_split<<<1024, 256, 0, s2>>>(emb, embh, embl,
                                    (size_t)NITEMS * HID, (size_t)NITEMS_PAD * HID);
    // t1^T[hid][node] = W1 @ emb[items]^T + b1
    gemm_sp<<<dim3(64, 2, 1), 256, SP_SMEM, s2>>>(w1h, w1l, HID, nullptr,
                                                  embh, embl, HID, items,
                                                  nullptr, xh, xl, NNODES, 0,
                                                  b1, nullptr, nullptr, NNODES, HID, 0);
    cudaEventRecord(evT1, s2);

    // s2: h-GEMM M-half0 (rows 0..4095) — needs adj half1 + t1
    cudaStreamWaitEvent(s2, evA1, 0);
    gemm_sp<<<dim3(2, 32, 2), 256, SP_SMEM, s2>>>(adjh, adjl, NNODES, nullptr,
                                                  xh, xl, NNODES, nullptr,
                                                  part, nullptr, nullptr, HID, NH,
                                                  nullptr, nullptr, nullptr, HID, NNODES / 2, 0);
    cudaEventRecord(evH0, s2);

    // stream 0: h-GEMM M-half1 (rows 4096..8191) — adj half2 ordered on s0; needs t1
    cudaStreamWaitEvent(0, evT1, 0);
    gemm_sp<<<dim3(2, 32, 2), 256, SP_SMEM, 0>>>(adjh + ADJ_HALF, adjl + ADJ_HALF, NNODES, nullptr,
                                                 xh, xl, NNODES, nullptr,
                                                 part + (size_t)(NNODES / 2) * HID,
                                                 nullptr, nullptr, HID, NH,
                                                 nullptr, nullptr, nullptr, HID, NNODES / 2, 0);
    // ---- join: both h halves complete on stream 0 ----
    cudaStreamWaitEvent(0, evH0, 0);
    combine2<<<NH / 1024, 256, 0, 0>>>(part, nullptr, hh, hl, 1);

    // t2^T = W2 @ h^T + b2
    gemm_sp<<<dim3(64, 2, 1), 256, SP_SMEM, 0>>>(w2h, w2l, HID, nullptr,
                                                 hh, hl, HID, nullptr,
                                                 nullptr, xh, xl, NNODES, 0,
                                                 b2, nullptr, nullptr, NNODES, HID, 0);
    // z = adj @ t2 -> z fp32 + zh/zl
    gemm_sp<<<dim3(2, 64, 2), 256, SP_SMEM, 0>>>(adjh, adjl, NNODES, nullptr,
                                                 xh, xl, NNODES, nullptr,
                                                 part, nullptr, nullptr, HID, NH,
                                                 nullptr, nullptr, nullptr, HID, NNODES / 2, 0);
    combine2<<<NH / 1024, 256, 0, 0>>>(part, z, zh, zl, 0);
    // q1s = z[last_item] @ Wf1^T + bf1
    gemm_sp<<<dim3(2, 4, 1), 256, SP_SMEM, 0>>>(zh, zl, HID, last_item,
                                                wf1h, wf1l, HID, nullptr,
                                                q1s, nullptr, nullptr, HID, 0,
                                                nullptr, bf1, nullptr, HID, HID, 0);
    // q2 = z @ Wf2^T + bf2
    gemm_sp<<<dim3(2, 64, 1), 256, SP_SMEM, 0>>>(zh, zl, HID, nullptr,
                                                 wf2h, wf2l, HID, nullptr,
                                                 q2, nullptr, nullptr, HID, 0,
                                                 nullptr, bf2, nullptr, HID, HID, 0);
    alpha_scatter<<<NNODES / 8, 256, 0, 0>>>(q1s, q2, z, Wf3, idx, sg);
    sh_kernel<<<BSESS, 256, 0, 0>>>(z, last_item, sg, wf4t, bf4, shh, shl);
    // logits + fused softmax partials (swapped grid for emb L2 reuse)
    gemm_sp<<<dim3(4, LG_GX, 1), 256, SP_SMEM, 0>>>(shh, shl, HID, nullptr,
                                                    embh, embl, HID, nullptr,
                                                    out, nullptr, nullptr, NITEMS, 0,
                                                    nullptr, nullptr, part, NITEMS, HID, 1);
    softmax_combine<<<BSESS, 256, 0, 0>>>(part, gmax, gsum);
    softmax_write<<<dim3((NITEMS / 4 + 255) / 256, BSESS), 256, 0, 0>>>(out, gmax, gsum);
}